// round 11
// baseline (speedup 1.0000x reference)
#include <cuda_runtime.h>
#include <cuda_fp16.h>
#include <math.h>
#include <stdint.h>

// Problem constants
#define BB 4
#define SS 2048
#define DD 1024
#define HH 16
#define DKH 64
#define MTOT (BB*SS)          // 8192 rows

#define L2E 1.4426950408889634f

// ---------------- scratch (static device globals; no allocation) -------------
__device__ __half g_Aq[MTOT*DD];
__device__ __half g_Ak[MTOT*DD];
__device__ __half g_Av[MTOT*DD];
__device__ __half g_Qh[MTOT*DD];
__device__ __half g_Kh[MTOT*DD];
__device__ __half g_Vh[MTOT*DD];
__device__ __half g_AOh[MTOT*DD];
__device__ __half g_Wq[DD*DD];     // WT[n][k] half (wq pre-scaled by 0.125)
__device__ __half g_Wk[DD*DD];
__device__ __half g_Wv[DD*DD];
__device__ __half g_Wo[DD*DD];

// ---------------- helpers -----------------------------------------------------
__device__ __forceinline__ uint32_t pkh2(float a, float b) {
    __half2 h = __floats2half2_rn(a, b);
    return *(uint32_t*)&h;
}
__device__ __forceinline__ uint32_t ex2h2(uint32_t x) {
    uint32_t r;
    asm("ex2.approx.f16x2 %0, %1;" : "=r"(r) : "r"(x));
    return r;
}
__device__ __forceinline__ void cpa16(uint32_t smem, const void* gmem) {
    asm volatile("cp.async.cg.shared.global [%0], [%1], 16;" :: "r"(smem), "l"(gmem));
}
__device__ __forceinline__ void cpa_commit() {
    asm volatile("cp.async.commit_group;");
}
template<int N> __device__ __forceinline__ void cpa_wait() {
    asm volatile("cp.async.wait_group %0;" :: "n"(N));
}
__device__ __forceinline__ uint32_t smem_u32(const void* p) {
    uint32_t a;
    asm("{ .reg .u64 t; cvta.to.shared.u64 t, %1; cvt.u32.u64 %0, t; }"
        : "=r"(a) : "l"(p));
    return a;
}
__device__ __forceinline__ void mma_f16(
    float c[4], const uint32_t a[4], const uint32_t b[2])
{
    asm volatile(
        "mma.sync.aligned.m16n8k16.row.col.f32.f16.f16.f32 "
        "{%0,%1,%2,%3}, {%4,%5,%6,%7}, {%8,%9}, {%0,%1,%2,%3};"
        : "+f"(c[0]), "+f"(c[1]), "+f"(c[2]), "+f"(c[3])
        : "r"(a[0]), "r"(a[1]), "r"(a[2]), "r"(a[3]),
          "r"(b[0]), "r"(b[1]));
}
__device__ __forceinline__ void ldsm4(
    uint32_t& r0, uint32_t& r1, uint32_t& r2, uint32_t& r3, uint32_t a)
{
    asm volatile("ldmatrix.sync.aligned.m8n8.x4.shared.b16 {%0,%1,%2,%3}, [%4];"
                 : "=r"(r0), "=r"(r1), "=r"(r2), "=r"(r3) : "r"(a));
}
__device__ __forceinline__ void ldsm4t(
    uint32_t& r0, uint32_t& r1, uint32_t& r2, uint32_t& r3, uint32_t a)
{
    asm volatile("ldmatrix.sync.aligned.m8n8.x4.trans.shared.b16 {%0,%1,%2,%3}, [%4];"
                 : "=r"(r0), "=r"(r1), "=r"(r2), "=r"(r3) : "r"(a));
}
__device__ __forceinline__ void stsm4(
    uint32_t a, uint32_t r0, uint32_t r1, uint32_t r2, uint32_t r3)
{
    asm volatile("stmatrix.sync.aligned.m8n8.x4.shared.b16 [%0], {%1,%2,%3,%4};"
                 :: "r"(a), "r"(r0), "r"(r1), "r"(r2), "r"(r3) : "memory");
}

// ---------------- prepass kernels (merged) ------------------------------------
__global__ __launch_bounds__(256) void act_conv_kernel(
    const float* __restrict__ q, const float* __restrict__ k,
    const float* __restrict__ v,
    __half* __restrict__ oq, __half* __restrict__ ok, __half* __restrict__ ov)
{
    const int which = blockIdx.y;
    const float* in = (which == 0) ? q : (which == 1) ? k : v;
    __half* out     = (which == 0) ? oq : (which == 1) ? ok : ov;
    int i = blockIdx.x * blockDim.x + threadIdx.x;
    float4 vv = ((const float4*)in)[i];
    uint2 o;
    o.x = pkh2(vv.x, vv.y);
    o.y = pkh2(vv.z, vv.w);
    ((uint2*)out)[i] = o;
}

// WT[n][k] = half(W[k][n] * scale); wq gets scale 0.125
__global__ __launch_bounds__(256) void wt_trans_kernel(
    const float* __restrict__ wq, const float* __restrict__ wk,
    const float* __restrict__ wv, const float* __restrict__ wo,
    __half* __restrict__ oq, __half* __restrict__ ok,
    __half* __restrict__ ov, __half* __restrict__ oo)
{
    const int which = blockIdx.z;
    const float* in = (which == 0) ? wq : (which == 1) ? wk : (which == 2) ? wv : wo;
    __half* out     = (which == 0) ? oq : (which == 1) ? ok : (which == 2) ? ov : oo;
    const float sc  = (which == 0) ? 0.125f : 1.0f;

    __shared__ float tl[32][33];
    const int tx = threadIdx.x, ty = threadIdx.y;
    const int n0 = blockIdx.x * 32, k0 = blockIdx.y * 32;
#pragma unroll
    for (int i = 0; i < 4; i++)
        tl[ty + i * 8][tx] = in[(size_t)(k0 + ty + i * 8) * DD + n0 + tx];
    __syncthreads();
#pragma unroll
    for (int i = 0; i < 4; i++)
        out[(size_t)(n0 + ty + i * 8) * DD + k0 + tx] =
            __float2half(tl[tx][ty + i * 8] * sc);
}

// =============================================================================
// FP16 HMMA GEMM (fused QKV): C = A @ WT^T + bias. blockIdx.z selects inputs.
// Fragments via ldmatrix.x4.
// =============================================================================
#define HP 72
#define ROWB (HP*2)                       // 144 bytes per smem row
#define G_STG_H (2 * 128 * HP)
#define G_SMEM (3 * G_STG_H * 2)          // 110592 bytes
#define GNT (DD / 64)                     // 16 K-iterations

__global__ __launch_bounds__(256) void gemm_qkv_f16(
    const __half* __restrict__ A0, const __half* __restrict__ A1,
    const __half* __restrict__ A2,
    const __half* __restrict__ W0, const __half* __restrict__ W1,
    const __half* __restrict__ W2,
    const float* __restrict__ b0, const float* __restrict__ b1,
    const float* __restrict__ b2,
    __half* __restrict__ C0, __half* __restrict__ C1, __half* __restrict__ C2)
{
    extern __shared__ __half shh[];

    const int z = blockIdx.z;
    const __half* A  = (z == 0) ? A0 : (z == 1) ? A1 : A2;
    const __half* WT = (z == 0) ? W0 : (z == 1) ? W1 : W2;
    const float* bias = (z == 0) ? b0 : (z == 1) ? b1 : b2;
    __half* C        = (z == 0) ? C0 : (z == 1) ? C1 : C2;
    const float bsc  = (z == 0) ? 0.125f : 1.0f;

    const int tid  = threadIdx.x;
    const int wid  = tid >> 5;
    const int lane = tid & 31;
    const int g    = lane >> 2;
    const int t    = lane & 3;
    const int wm   = (wid & 3) << 5;
    const int wn   = (wid >> 2) << 6;
    const int m0   = blockIdx.y << 7;
    const int n0   = blockIdx.x << 7;

    const int lj = lane >> 3, lr = lane & 7;
    uint32_t aoff[2], boff[4];
#pragma unroll
    for (int mi = 0; mi < 2; mi++)
        aoff[mi] = (uint32_t)(((wm + (mi << 4) + ((lj & 1) << 3) + lr) * HP
                               + ((lj >> 1) << 3)) * 2);
#pragma unroll
    for (int np = 0; np < 4; np++)
        boff[np] = (uint32_t)(((wn + (np << 4) + ((lj & 1) << 3) + lr) * HP
                               + ((lj >> 1) << 3)) * 2);

    float c[2][8][4];
#pragma unroll
    for (int mi = 0; mi < 2; mi++)
#pragma unroll
        for (int ni = 0; ni < 8; ni++)
#pragma unroll
            for (int j = 0; j < 4; j++) c[mi][ni][j] = 0.f;

    const uint32_t shbase = smem_u32(shh);

    auto load_tile = [&](int kt, int stg) {
        const int k0 = kt << 6;
        const uint32_t sa = shbase + (stg * G_STG_H) * 2;
        const uint32_t sb = sa + 128 * ROWB;
#pragma unroll
        for (int j = 0; j < 4; j++) {
            int ca = j * 256 + tid;
            int row = ca >> 3, k8 = ca & 7;
            cpa16(sa + row * ROWB + (k8 << 4),
                  A + (size_t)(m0 + row) * DD + k0 + (k8 << 3));
        }
#pragma unroll
        for (int j = 0; j < 4; j++) {
            int cb = j * 256 + tid;
            int row = cb >> 3, k8 = cb & 7;
            cpa16(sb + row * ROWB + (k8 << 4),
                  WT + (size_t)(n0 + row) * DD + k0 + (k8 << 3));
        }
        cpa_commit();
    };

    load_tile(0, 0);
    load_tile(1, 1);

    for (int kt = 0; kt < GNT; kt++) {
        if (kt + 1 < GNT) cpa_wait<1>(); else cpa_wait<0>();
        __syncthreads();
        if (kt + 2 < GNT) load_tile(kt + 2, (kt + 2) % 3);

        const int stg = kt % 3;
        const uint32_t sa = shbase + (stg * G_STG_H) * 2;
        const uint32_t sb = sa + 128 * ROWB;

#pragma unroll
        for (int ks = 0; ks < 4; ks++) {
            uint32_t a[2][4], b[8][2];
#pragma unroll
            for (int mi = 0; mi < 2; mi++)
                ldsm4(a[mi][0], a[mi][1], a[mi][2], a[mi][3],
                      sa + aoff[mi] + ks * 32);
#pragma unroll
            for (int np = 0; np < 4; np++)
                ldsm4(b[2*np][0], b[2*np+1][0], b[2*np][1], b[2*np+1][1],
                      sb + boff[np] + ks * 32);
#pragma unroll
            for (int mi = 0; mi < 2; mi++)
#pragma unroll
                for (int ni = 0; ni < 8; ni++)
                    mma_f16(c[mi][ni], a[mi], b[ni]);
        }
    }

#pragma unroll
    for (int ni = 0; ni < 8; ni++) {
        int col = n0 + wn + (ni << 3) + (t << 1);
        float2 bv = *(const float2*)(bias + col);
        bv.x *= bsc; bv.y *= bsc;
#pragma unroll
        for (int mi = 0; mi < 2; mi++) {
            int row = m0 + wm + (mi << 4) + g;
            *(uint32_t*)(C + (size_t)row       * DD + col) =
                pkh2(c[mi][ni][0] + bv.x, c[mi][ni][1] + bv.y);
            *(uint32_t*)(C + (size_t)(row + 8) * DD + col) =
                pkh2(c[mi][ni][2] + bv.x, c[mi][ni][3] + bv.y);
        }
    }
}

// Single GEMM (output projection, fp32 out) — same core.
__global__ __launch_bounds__(256) void gemm_o_f16(
    const __half* __restrict__ A, const __half* __restrict__ WT,
    const float* __restrict__ bias, float* __restrict__ C)
{
    extern __shared__ __half shh[];

    const int tid  = threadIdx.x;
    const int wid  = tid >> 5;
    const int lane = tid & 31;
    const int g    = lane >> 2;
    const int t    = lane & 3;
    const int wm   = (wid & 3) << 5;
    const int wn   = (wid >> 2) << 6;
    const int m0   = blockIdx.y << 7;
    const int n0   = blockIdx.x << 7;

    const int lj = lane >> 3, lr = lane & 7;
    uint32_t aoff[2], boff[4];
#pragma unroll
    for (int mi = 0; mi < 2; mi++)
        aoff[mi] = (uint32_t)(((wm + (mi << 4) + ((lj & 1) << 3) + lr) * HP
                               + ((lj >> 1) << 3)) * 2);
#pragma unroll
    for (int np = 0; np < 4; np++)
        boff[np] = (uint32_t)(((wn + (np << 4) + ((lj & 1) << 3) + lr) * HP
                               + ((lj >> 1) << 3)) * 2);

    float c[2][8][4];
#pragma unroll
    for (int mi = 0; mi < 2; mi++)
#pragma unroll
        for (int ni = 0; ni < 8; ni++)
#pragma unroll
            for (int j = 0; j < 4; j++) c[mi][ni][j] = 0.f;

    const uint32_t shbase = smem_u32(shh);

    auto load_tile = [&](int kt, int stg) {
        const int k0 = kt << 6;
        const uint32_t sa = shbase + (stg * G_STG_H) * 2;
        const uint32_t sb = sa + 128 * ROWB;
#pragma unroll
        for (int j = 0; j < 4; j++) {
            int ca = j * 256 + tid;
            int row = ca >> 3, k8 = ca & 7;
            cpa16(sa + row * ROWB + (k8 << 4),
                  A + (size_t)(m0 + row) * DD + k0 + (k8 << 3));
        }
#pragma unroll
        for (int j = 0; j < 4; j++) {
            int cb = j * 256 + tid;
            int row = cb >> 3, k8 = cb & 7;
            cpa16(sb + row * ROWB + (k8 << 4),
                  WT + (size_t)(n0 + row) * DD + k0 + (k8 << 3));
        }
        cpa_commit();
    };

    load_tile(0, 0);
    load_tile(1, 1);

    for (int kt = 0; kt < GNT; kt++) {
        if (kt + 1 < GNT) cpa_wait<1>(); else cpa_wait<0>();
        __syncthreads();
        if (kt + 2 < GNT) load_tile(kt + 2, (kt + 2) % 3);

        const int stg = kt % 3;
        const uint32_t sa = shbase + (stg * G_STG_H) * 2;
        const uint32_t sb = sa + 128 * ROWB;

#pragma unroll
        for (int ks = 0; ks < 4; ks++) {
            uint32_t a[2][4], b[8][2];
#pragma unroll
            for (int mi = 0; mi < 2; mi++)
                ldsm4(a[mi][0], a[mi][1], a[mi][2], a[mi][3],
                      sa + aoff[mi] + ks * 32);
#pragma unroll
            for (int np = 0; np < 4; np++)
                ldsm4(b[2*np][0], b[2*np+1][0], b[2*np][1], b[2*np+1][1],
                      sb + boff[np] + ks * 32);
#pragma unroll
            for (int mi = 0; mi < 2; mi++)
#pragma unroll
                for (int ni = 0; ni < 8; ni++)
                    mma_f16(c[mi][ni], a[mi], b[ni]);
        }
    }

#pragma unroll
    for (int ni = 0; ni < 8; ni++) {
        int col = n0 + wn + (ni << 3) + (t << 1);
        float2 bv = *(const float2*)(bias + col);
#pragma unroll
        for (int mi = 0; mi < 2; mi++) {
            int row = m0 + wm + (mi << 4) + g;
            float2 v0 = make_float2(c[mi][ni][0] + bv.x, c[mi][ni][1] + bv.y);
            float2 v1 = make_float2(c[mi][ni][2] + bv.x, c[mi][ni][3] + bv.y);
            *(float2*)(C + (size_t)row       * DD + col) = v0;
            *(float2*)(C + (size_t)(row + 8) * DD + col) = v1;
        }
    }
}

// =============================================================================
// FP16 flash attention (causal), 256 threads / 8 warps, warp tile 16x64.
// ldmatrix/stmatrix fragments, ex2.f16x2 softmax, ones-MMA rowsum,
// cp.async double-buffered K/V. Smem 73.7 KB; launch_bounds(256,2).
// =============================================================================
#define ATT_SMEM ((128*HP + 2*64*HP + 2*64*HP + 128*HP) * 2)

__global__ __launch_bounds__(256, 2) void flash_f16_kernel(
    const __half* __restrict__ Q, const __half* __restrict__ K,
    const __half* __restrict__ V, __half* __restrict__ O)
{
    const int qt = (SS / 128 - 1) - blockIdx.x;
    const int h  = blockIdx.y;
    const int b  = blockIdx.z;
    const int tid  = threadIdx.x;
    const int warp = tid >> 5;
    const int lane = tid & 31;
    const int g    = lane >> 2;
    const int t    = lane & 3;
    const int wm   = warp << 4;          // 16 rows per warp

    extern __shared__ __half smh[];
    __half* Qs = smh;                    // [128][HP]
    __half* Ks = Qs + 128 * HP;          // [2][64][HP]
    __half* Vs = Ks + 2 * 64 * HP;       // [2][64][HP]
    __half* Ps = Vs + 2 * 64 * HP;       // [128][HP]

    const uint32_t qsb = smem_u32(Qs);
    const uint32_t ksbase = smem_u32(Ks);
    const uint32_t vsbase = smem_u32(Vs);
    const uint32_t psb = smem_u32(Ps);

    // ldmatrix/stmatrix per-lane offsets (16-row warp tile)
    const int lj = lane >> 3, lr = lane & 7;
    const uint32_t moff = (uint32_t)(((wm + ((lj & 1) << 3) + lr) * HP
                                      + ((lj >> 1) << 3)) * 2);
    uint32_t koff[4];
#pragma unroll
    for (int np = 0; np < 4; np++)
        koff[np] = (uint32_t)((((np << 4) + ((lj & 1) << 3) + lr) * HP
                               + ((lj >> 1) << 3)) * 2);

    const int vrow = ((lane >> 3) & 1) * 8 + (lane & 7);
    const int vcol = (lane >> 4) * 8;

    const __half* Kh0 = K + ((size_t)(b * SS)) * DD + h * DKH;
    const __half* Vh0 = V + ((size_t)(b * SS)) * DD + h * DKH;

    auto load_kv = [&](int kt, int buf) {
        const __half* Kb = Kh0 + (size_t)(kt * 64) * DD;
        const __half* Vb = Vh0 + (size_t)(kt * 64) * DD;
        const uint32_t kb = ksbase + buf * 64 * ROWB;
        const uint32_t vb = vsbase + buf * 64 * ROWB;
#pragma unroll
        for (int i = 0; i < 2; i++) {
            int e = i * 256 + tid;
            int r = e >> 3;
            int c8 = e & 7;
            cpa16(kb + r * ROWB + (c8 << 4), Kb + (size_t)r * DD + (c8 << 3));
            cpa16(vb + r * ROWB + (c8 << 4), Vb + (size_t)r * DD + (c8 << 3));
        }
        cpa_commit();
    };

    // ---- load Q tile (128x64 halfs, 256 threads) ----
    const __half* Qb = Q + ((size_t)(b * SS + qt * 128)) * DD + h * DKH;
#pragma unroll
    for (int i = 0; i < 4; i++) {
        int e = i * 256 + tid;
        int r = e >> 3;
        int c8 = e & 7;
        *(uint4*)&Qs[r * HP + (c8 << 3)] = *(const uint4*)(Qb + (size_t)r * DD + (c8 << 3));
    }

    load_kv(0, 0);

    float m_i[2], l_i[2], co[8][4];
#pragma unroll
    for (int hh = 0; hh < 2; hh++) { m_i[hh] = -INFINITY; l_i[hh] = 0.f; }
#pragma unroll
    for (int ni = 0; ni < 8; ni++)
#pragma unroll
        for (int j = 0; j < 4; j++) co[ni][j] = 0.f;

    const uint32_t bones = 0x3C003C00u;  // half2(1,1)
    const int ktmax = 2 * qt + 1;

    for (int kt = 0; kt <= ktmax; kt++) {
        __syncthreads();
        if (kt < ktmax) {
            load_kv(kt + 1, (kt + 1) & 1);
            cpa_wait<1>();
        } else {
            cpa_wait<0>();
        }
        __syncthreads();

        const uint32_t ktile = ksbase + (kt & 1) * 64 * ROWB;
        const uint32_t vtile = vsbase + (kt & 1) * 64 * ROWB;

        // ---- S = Q K^T (pre-scaled via wq) ----
        float cs[8][4];
#pragma unroll
        for (int ni = 0; ni < 8; ni++)
#pragma unroll
            for (int j = 0; j < 4; j++) cs[ni][j] = 0.f;

#pragma unroll
        for (int ks = 0; ks < 4; ks++) {
            uint32_t a[4], bf[8][2];
            ldsm4(a[0], a[1], a[2], a[3], qsb + moff + ks * 32);
#pragma unroll
            for (int np = 0; np < 4; np++)
                ldsm4(bf[2*np][0], bf[2*np+1][0], bf[2*np][1], bf[2*np+1][1],
                      ktile + koff[np] + ks * 32);
#pragma unroll
            for (int ni = 0; ni < 8; ni++)
                mma_f16(cs[ni], a, bf[ni]);
        }

        // ---- causal mask (only last two tiles) ----
        if (kt >= 2 * qt) {
#pragma unroll
            for (int ni = 0; ni < 8; ni++)
#pragma unroll
                for (int j = 0; j < 4; j++) {
                    int row = qt * 128 + wm + g + ((j >> 1) << 3);
                    int col = kt * 64 + (ni << 3) + (t << 1) + (j & 1);
                    if (col > row) cs[ni][j] = -1e9f;
                }
        }

        // ---- online softmax: max + alpha ----
        float ml[2], al[2];
#pragma unroll
        for (int hh = 0; hh < 2; hh++) {
            float mx = -INFINITY;
#pragma unroll
            for (int ni = 0; ni < 8; ni++)
                mx = fmaxf(mx, fmaxf(cs[ni][2*hh], cs[ni][2*hh+1]));
            mx = fmaxf(mx, __shfl_xor_sync(0xffffffffu, mx, 1));
            mx = fmaxf(mx, __shfl_xor_sync(0xffffffffu, mx, 2));
            float m2 = fmaxf(m_i[hh], mx);
            al[hh] = __expf(m_i[hh] - m2);
            m_i[hh] = m2;
            ml[hh] = m2 * L2E;
        }
#pragma unroll
        for (int ni = 0; ni < 8; ni++)
#pragma unroll
            for (int j = 0; j < 4; j++)
                co[ni][j] *= al[j >> 1];

        // ---- P = exp2(S*log2e - m*log2e) in half; stmatrix ----
#pragma unroll
        for (int np = 0; np < 4; np++) {
            int ni = 2 * np, ni1 = 2 * np + 1;
            uint32_t r0 = ex2h2(pkh2(fmaf(cs[ni ][0], L2E, -ml[0]),
                                     fmaf(cs[ni ][1], L2E, -ml[0])));
            uint32_t r1 = ex2h2(pkh2(fmaf(cs[ni ][2], L2E, -ml[1]),
                                     fmaf(cs[ni ][3], L2E, -ml[1])));
            uint32_t r2 = ex2h2(pkh2(fmaf(cs[ni1][0], L2E, -ml[0]),
                                     fmaf(cs[ni1][1], L2E, -ml[0])));
            uint32_t r3 = ex2h2(pkh2(fmaf(cs[ni1][2], L2E, -ml[1]),
                                     fmaf(cs[ni1][3], L2E, -ml[1])));
            stsm4(psb + moff + np * 32, r0, r1, r2, r3);
        }
        __syncwarp();

        // ---- O += P @ V  and  l-rowsum via MMA with ones ----
        float csum[4];
#pragma unroll
        for (int j = 0; j < 4; j++) csum[j] = 0.f;

#pragma unroll
        for (int ks = 0; ks < 4; ks++) {
            uint32_t a[4], bf[8][2];
            ldsm4(a[0], a[1], a[2], a[3], psb + moff + ks * 32);
#pragma unroll
            for (int nn = 0; nn < 4; nn++) {
                uint32_t addr = vtile + ((ks << 4) + vrow) * ROWB + ((nn << 4) + vcol) * 2;
                ldsm4t(bf[2*nn][0], bf[2*nn][1], bf[2*nn+1][0], bf[2*nn+1][1], addr);
            }
            uint32_t bo[2] = {bones, bones};
            mma_f16(csum, a, bo);
#pragma unroll
            for (int ni = 0; ni < 8; ni++)
                mma_f16(co[ni], a, bf[ni]);
        }

#pragma unroll
        for (int hh = 0; hh < 2; hh++)
            l_i[hh] = l_i[hh] * al[hh] + csum[2*hh];
    }

    // ---- epilogue ----
#pragma unroll
    for (int hh = 0; hh < 2; hh++) {
        float inv = 1.f / l_i[hh];
        int row = qt * 128 + wm + g + (hh << 3);
        __half* ob = O + ((size_t)(b * SS + row)) * DD + h * DKH;
#pragma unroll
        for (int ni = 0; ni < 8; ni++) {
            int col = (ni << 3) + (t << 1);
            *(uint32_t*)(ob + col) = pkh2(co[ni][2*hh] * inv,
                                          co[ni][2*hh+1] * inv);
        }
    }
}

// =============================================================================
// Launch
// =============================================================================
extern "C" void kernel_launch(void* const* d_in, const int* in_sizes, int n_in,
                              void* d_out, int out_size)
{
    const float* q  = (const float*)d_in[1];
    const float* k  = (const float*)d_in[2];
    const float* v  = (const float*)d_in[3];
    const float* wq = (const float*)d_in[5];
    const float* bq = (const float*)d_in[6];
    const float* wk = (const float*)d_in[7];
    const float* bk = (const float*)d_in[8];
    const float* wv = (const float*)d_in[9];
    const float* bv = (const float*)d_in[10];
    const float* wo = (const float*)d_in[11];
    const float* bo = (const float*)d_in[12];
    float* out = (float*)d_out;

    __half *aq, *ak, *av, *qh, *kh, *vh, *aoh, *wtq, *wtk, *wtv, *wto;
    cudaGetSymbolAddress((void**)&aq,  g_Aq);
    cudaGetSymbolAddress((void**)&ak,  g_Ak);
    cudaGetSymbolAddress((void**)&av,  g_Av);
    cudaGetSymbolAddress((void**)&qh,  g_Qh);
    cudaGetSymbolAddress((void**)&kh,  g_Kh);
    cudaGetSymbolAddress((void**)&vh,  g_Vh);
    cudaGetSymbolAddress((void**)&aoh, g_AOh);
    cudaGetSymbolAddress((void**)&wtq, g_Wq);
    cudaGetSymbolAddress((void**)&wtk, g_Wk);
    cudaGetSymbolAddress((void**)&wtv, g_Wv);
    cudaGetSymbolAddress((void**)&wto, g_Wo);

    cudaFuncSetAttribute(flash_f16_kernel,
                         cudaFuncAttributeMaxDynamicSharedMemorySize, ATT_SMEM);
    cudaFuncSetAttribute(gemm_qkv_f16,
                         cudaFuncAttributeMaxDynamicSharedMemorySize, G_SMEM);
    cudaFuncSetAttribute(gemm_o_f16,
                         cudaFuncAttributeMaxDynamicSharedMemorySize, G_SMEM);

    // ---- prepass (2 launches) ----
    const int nA4 = MTOT * DD / 4;
    act_conv_kernel<<<dim3(nA4 / 256, 3), 256>>>(q, k, v, aq, ak, av);
    wt_trans_kernel<<<dim3(DD / 32, DD / 32, 4), dim3(32, 8)>>>(
        wq, wk, wv, wo, wtq, wtk, wtv, wto);

    // ---- fused QKV projections ----
    dim3 gblk(256);
    dim3 gqkv(DD / 128, MTOT / 128, 3);   // (8, 64, 3)
    gemm_qkv_f16<<<gqkv, gblk, G_SMEM>>>(aq, ak, av, wtq, wtk, wtv,
                                         bq, bk, bv, qh, kh, vh);

    // ---- attention (256 threads, 8 warps) ----
    dim3 agrid(SS / 128, HH, BB);         // (16, 16, 4)
    flash_f16_kernel<<<agrid, dim3(256), ATT_SMEM>>>(qh, kh, vh, aoh);

    // ---- output projection (fp32 out) ----
    dim3 go(DD / 128, MTOT / 128);
    gemm_o_f16<<<go, gblk, G_SMEM>>>(aoh, wto, bo, out);
}

// round 12
// speedup vs baseline: 1.0087x; 1.0087x over previous
#include <cuda_runtime.h>
#include <cuda_fp16.h>
#include <math.h>
#include <stdint.h>

// Problem constants
#define BB 4
#define SS 2048
#define DD 1024
#define HH 16
#define DKH 64
#define MTOT (BB*SS)          // 8192 rows

#define L2E 1.4426950408889634f

// ---------------- scratch (static device globals; no allocation) -------------
__device__ __half g_Aq[MTOT*DD];
__device__ __half g_Ak[MTOT*DD];
__device__ __half g_Av[MTOT*DD];
__device__ __half g_Qh[MTOT*DD];
__device__ __half g_Kh[MTOT*DD];
__device__ __half g_Vh[MTOT*DD];
__device__ __half g_AOh[MTOT*DD];
__device__ __half g_Wq[DD*DD];     // WT[n][k] half (wq pre-scaled by 0.125)
__device__ __half g_Wk[DD*DD];
__device__ __half g_Wv[DD*DD];
__device__ __half g_Wo[DD*DD];

// ---------------- helpers -----------------------------------------------------
__device__ __forceinline__ uint32_t pkh2(float a, float b) {
    __half2 h = __floats2half2_rn(a, b);
    return *(uint32_t*)&h;
}
__device__ __forceinline__ uint32_t ex2h2(uint32_t x) {
    uint32_t r;
    asm("ex2.approx.f16x2 %0, %1;" : "=r"(r) : "r"(x));
    return r;
}
__device__ __forceinline__ void cpa16(uint32_t smem, const void* gmem) {
    asm volatile("cp.async.cg.shared.global [%0], [%1], 16;" :: "r"(smem), "l"(gmem));
}
__device__ __forceinline__ void cpa_commit() {
    asm volatile("cp.async.commit_group;");
}
template<int N> __device__ __forceinline__ void cpa_wait() {
    asm volatile("cp.async.wait_group %0;" :: "n"(N));
}
__device__ __forceinline__ uint32_t smem_u32(const void* p) {
    uint32_t a;
    asm("{ .reg .u64 t; cvta.to.shared.u64 t, %1; cvt.u32.u64 %0, t; }"
        : "=r"(a) : "l"(p));
    return a;
}
__device__ __forceinline__ void mma_f16(
    float c[4], const uint32_t a[4], const uint32_t b[2])
{
    asm volatile(
        "mma.sync.aligned.m16n8k16.row.col.f32.f16.f16.f32 "
        "{%0,%1,%2,%3}, {%4,%5,%6,%7}, {%8,%9}, {%0,%1,%2,%3};"
        : "+f"(c[0]), "+f"(c[1]), "+f"(c[2]), "+f"(c[3])
        : "r"(a[0]), "r"(a[1]), "r"(a[2]), "r"(a[3]),
          "r"(b[0]), "r"(b[1]));
}
__device__ __forceinline__ void ldsm4(
    uint32_t& r0, uint32_t& r1, uint32_t& r2, uint32_t& r3, uint32_t a)
{
    asm volatile("ldmatrix.sync.aligned.m8n8.x4.shared.b16 {%0,%1,%2,%3}, [%4];"
                 : "=r"(r0), "=r"(r1), "=r"(r2), "=r"(r3) : "r"(a));
}
__device__ __forceinline__ void ldsm4t(
    uint32_t& r0, uint32_t& r1, uint32_t& r2, uint32_t& r3, uint32_t a)
{
    asm volatile("ldmatrix.sync.aligned.m8n8.x4.trans.shared.b16 {%0,%1,%2,%3}, [%4];"
                 : "=r"(r0), "=r"(r1), "=r"(r2), "=r"(r3) : "r"(a));
}
__device__ __forceinline__ void stsm4(
    uint32_t a, uint32_t r0, uint32_t r1, uint32_t r2, uint32_t r3)
{
    asm volatile("stmatrix.sync.aligned.m8n8.x4.shared.b16 [%0], {%1,%2,%3,%4};"
                 :: "r"(a), "r"(r0), "r"(r1), "r"(r2), "r"(r3) : "memory");
}

// ---------------- prepass kernels (merged) ------------------------------------
__global__ __launch_bounds__(256) void act_conv_kernel(
    const float* __restrict__ q, const float* __restrict__ k,
    const float* __restrict__ v,
    __half* __restrict__ oq, __half* __restrict__ ok, __half* __restrict__ ov)
{
    const int which = blockIdx.y;
    const float* in = (which == 0) ? q : (which == 1) ? k : v;
    __half* out     = (which == 0) ? oq : (which == 1) ? ok : ov;
    int i = blockIdx.x * blockDim.x + threadIdx.x;
    float4 vv = ((const float4*)in)[i];
    uint2 o;
    o.x = pkh2(vv.x, vv.y);
    o.y = pkh2(vv.z, vv.w);
    ((uint2*)out)[i] = o;
}

// WT[n][k] = half(W[k][n] * scale); wq gets scale 0.125
__global__ __launch_bounds__(256) void wt_trans_kernel(
    const float* __restrict__ wq, const float* __restrict__ wk,
    const float* __restrict__ wv, const float* __restrict__ wo,
    __half* __restrict__ oq, __half* __restrict__ ok,
    __half* __restrict__ ov, __half* __restrict__ oo)
{
    const int which = blockIdx.z;
    const float* in = (which == 0) ? wq : (which == 1) ? wk : (which == 2) ? wv : wo;
    __half* out     = (which == 0) ? oq : (which == 1) ? ok : (which == 2) ? ov : oo;
    const float sc  = (which == 0) ? 0.125f : 1.0f;

    __shared__ float tl[32][33];
    const int tx = threadIdx.x, ty = threadIdx.y;
    const int n0 = blockIdx.x * 32, k0 = blockIdx.y * 32;
#pragma unroll
    for (int i = 0; i < 4; i++)
        tl[ty + i * 8][tx] = in[(size_t)(k0 + ty + i * 8) * DD + n0 + tx];
    __syncthreads();
#pragma unroll
    for (int i = 0; i < 4; i++)
        out[(size_t)(n0 + ty + i * 8) * DD + k0 + tx] =
            __float2half(tl[tx][ty + i * 8] * sc);
}

// =============================================================================
// Persistent FP16 HMMA GEMM (fused QKV): 296 CTAs loop over 1536 tiles
// (z, m, n). Block tile 128x128, K-tile 64, ldmatrix fragments, 3-stage
// cp.async ring. Tail shrinks from a partial wave to a partial tile.
// =============================================================================
#define HP 72
#define ROWB (HP*2)                       // 144 bytes per smem row
#define G_STG_H (2 * 128 * HP)
#define G_SMEM (3 * G_STG_H * 2)          // 110592 bytes
#define GNT (DD / 64)                     // 16 K-iterations
#define PGRID 296                         // 2 CTAs/SM * 148 SMs

__global__ __launch_bounds__(256) void gemm_qkv_f16(
    const __half* __restrict__ A0, const __half* __restrict__ A1,
    const __half* __restrict__ A2,
    const __half* __restrict__ W0, const __half* __restrict__ W1,
    const __half* __restrict__ W2,
    const float* __restrict__ b0, const float* __restrict__ b1,
    const float* __restrict__ b2,
    __half* __restrict__ C0, __half* __restrict__ C1, __half* __restrict__ C2)
{
    extern __shared__ __half shh[];

    const int tid  = threadIdx.x;
    const int wid  = tid >> 5;
    const int lane = tid & 31;
    const int g    = lane >> 2;
    const int t    = lane & 3;
    const int wm   = (wid & 3) << 5;
    const int wn   = (wid >> 2) << 6;

    const int lj = lane >> 3, lr = lane & 7;
    uint32_t aoff[2], boff[4];
#pragma unroll
    for (int mi = 0; mi < 2; mi++)
        aoff[mi] = (uint32_t)(((wm + (mi << 4) + ((lj & 1) << 3) + lr) * HP
                               + ((lj >> 1) << 3)) * 2);
#pragma unroll
    for (int np = 0; np < 4; np++)
        boff[np] = (uint32_t)(((wn + (np << 4) + ((lj & 1) << 3) + lr) * HP
                               + ((lj >> 1) << 3)) * 2);

    const uint32_t shbase = smem_u32(shh);

    for (int idx = blockIdx.x; idx < 1536; idx += gridDim.x) {
        const int z   = idx >> 9;            // /512
        const int rem = idx & 511;
        const int m0  = (rem >> 3) << 7;
        const int n0  = (rem & 7) << 7;

        const __half* A  = (z == 0) ? A0 : (z == 1) ? A1 : A2;
        const __half* WT = (z == 0) ? W0 : (z == 1) ? W1 : W2;
        const float* bias = (z == 0) ? b0 : (z == 1) ? b1 : b2;
        __half* C        = (z == 0) ? C0 : (z == 1) ? C1 : C2;
        const float bsc  = (z == 0) ? 0.125f : 1.0f;

        __syncthreads();   // previous tile's smem reads complete

        auto load_tile = [&](int kt, int stg) {
            const int k0 = kt << 6;
            const uint32_t sa = shbase + (stg * G_STG_H) * 2;
            const uint32_t sb = sa + 128 * ROWB;
#pragma unroll
            for (int j = 0; j < 4; j++) {
                int ca = j * 256 + tid;
                int row = ca >> 3, k8 = ca & 7;
                cpa16(sa + row * ROWB + (k8 << 4),
                      A + (size_t)(m0 + row) * DD + k0 + (k8 << 3));
            }
#pragma unroll
            for (int j = 0; j < 4; j++) {
                int cb = j * 256 + tid;
                int row = cb >> 3, k8 = cb & 7;
                cpa16(sb + row * ROWB + (k8 << 4),
                      WT + (size_t)(n0 + row) * DD + k0 + (k8 << 3));
            }
            cpa_commit();
        };

        float c[2][8][4];
#pragma unroll
        for (int mi = 0; mi < 2; mi++)
#pragma unroll
            for (int ni = 0; ni < 8; ni++)
#pragma unroll
                for (int j = 0; j < 4; j++) c[mi][ni][j] = 0.f;

        load_tile(0, 0);
        load_tile(1, 1);

        for (int kt = 0; kt < GNT; kt++) {
            if (kt + 1 < GNT) cpa_wait<1>(); else cpa_wait<0>();
            __syncthreads();
            if (kt + 2 < GNT) load_tile(kt + 2, (kt + 2) % 3);

            const int stg = kt % 3;
            const uint32_t sa = shbase + (stg * G_STG_H) * 2;
            const uint32_t sb = sa + 128 * ROWB;

#pragma unroll
            for (int ks = 0; ks < 4; ks++) {
                uint32_t a[2][4], b[8][2];
#pragma unroll
                for (int mi = 0; mi < 2; mi++)
                    ldsm4(a[mi][0], a[mi][1], a[mi][2], a[mi][3],
                          sa + aoff[mi] + ks * 32);
#pragma unroll
                for (int np = 0; np < 4; np++)
                    ldsm4(b[2*np][0], b[2*np+1][0], b[2*np][1], b[2*np+1][1],
                          sb + boff[np] + ks * 32);
#pragma unroll
                for (int mi = 0; mi < 2; mi++)
#pragma unroll
                    for (int ni = 0; ni < 8; ni++)
                        mma_f16(c[mi][ni], a[mi], b[ni]);
            }
        }

#pragma unroll
        for (int ni = 0; ni < 8; ni++) {
            int col = n0 + wn + (ni << 3) + (t << 1);
            float2 bv = *(const float2*)(bias + col);
            bv.x *= bsc; bv.y *= bsc;
#pragma unroll
            for (int mi = 0; mi < 2; mi++) {
                int row = m0 + wm + (mi << 4) + g;
                *(uint32_t*)(C + (size_t)row       * DD + col) =
                    pkh2(c[mi][ni][0] + bv.x, c[mi][ni][1] + bv.y);
                *(uint32_t*)(C + (size_t)(row + 8) * DD + col) =
                    pkh2(c[mi][ni][2] + bv.x, c[mi][ni][3] + bv.y);
            }
        }
    }
}

// Persistent single GEMM (output projection, fp32 out): 296 CTAs, 512 tiles.
__global__ __launch_bounds__(256) void gemm_o_f16(
    const __half* __restrict__ A, const __half* __restrict__ WT,
    const float* __restrict__ bias, float* __restrict__ C)
{
    extern __shared__ __half shh[];

    const int tid  = threadIdx.x;
    const int wid  = tid >> 5;
    const int lane = tid & 31;
    const int g    = lane >> 2;
    const int t    = lane & 3;
    const int wm   = (wid & 3) << 5;
    const int wn   = (wid >> 2) << 6;

    const int lj = lane >> 3, lr = lane & 7;
    uint32_t aoff[2], boff[4];
#pragma unroll
    for (int mi = 0; mi < 2; mi++)
        aoff[mi] = (uint32_t)(((wm + (mi << 4) + ((lj & 1) << 3) + lr) * HP
                               + ((lj >> 1) << 3)) * 2);
#pragma unroll
    for (int np = 0; np < 4; np++)
        boff[np] = (uint32_t)(((wn + (np << 4) + ((lj & 1) << 3) + lr) * HP
                               + ((lj >> 1) << 3)) * 2);

    const uint32_t shbase = smem_u32(shh);

    for (int idx = blockIdx.x; idx < 512; idx += gridDim.x) {
        const int m0 = (idx >> 3) << 7;
        const int n0 = (idx & 7) << 7;

        __syncthreads();

        auto load_tile = [&](int kt, int stg) {
            const int k0 = kt << 6;
            const uint32_t sa = shbase + (stg * G_STG_H) * 2;
            const uint32_t sb = sa + 128 * ROWB;
#pragma unroll
            for (int j = 0; j < 4; j++) {
                int ca = j * 256 + tid;
                int row = ca >> 3, k8 = ca & 7;
                cpa16(sa + row * ROWB + (k8 << 4),
                      A + (size_t)(m0 + row) * DD + k0 + (k8 << 3));
            }
#pragma unroll
            for (int j = 0; j < 4; j++) {
                int cb = j * 256 + tid;
                int row = cb >> 3, k8 = cb & 7;
                cpa16(sb + row * ROWB + (k8 << 4),
                      WT + (size_t)(n0 + row) * DD + k0 + (k8 << 3));
            }
            cpa_commit();
        };

        float c[2][8][4];
#pragma unroll
        for (int mi = 0; mi < 2; mi++)
#pragma unroll
            for (int ni = 0; ni < 8; ni++)
#pragma unroll
                for (int j = 0; j < 4; j++) c[mi][ni][j] = 0.f;

        load_tile(0, 0);
        load_tile(1, 1);

        for (int kt = 0; kt < GNT; kt++) {
            if (kt + 1 < GNT) cpa_wait<1>(); else cpa_wait<0>();
            __syncthreads();
            if (kt + 2 < GNT) load_tile(kt + 2, (kt + 2) % 3);

            const int stg = kt % 3;
            const uint32_t sa = shbase + (stg * G_STG_H) * 2;
            const uint32_t sb = sa + 128 * ROWB;

#pragma unroll
            for (int ks = 0; ks < 4; ks++) {
                uint32_t a[2][4], b[8][2];
#pragma unroll
                for (int mi = 0; mi < 2; mi++)
                    ldsm4(a[mi][0], a[mi][1], a[mi][2], a[mi][3],
                          sa + aoff[mi] + ks * 32);
#pragma unroll
                for (int np = 0; np < 4; np++)
                    ldsm4(b[2*np][0], b[2*np+1][0], b[2*np][1], b[2*np+1][1],
                          sb + boff[np] + ks * 32);
#pragma unroll
                for (int mi = 0; mi < 2; mi++)
#pragma unroll
                    for (int ni = 0; ni < 8; ni++)
                        mma_f16(c[mi][ni], a[mi], b[ni]);
            }
        }

#pragma unroll
        for (int ni = 0; ni < 8; ni++) {
            int col = n0 + wn + (ni << 3) + (t << 1);
            float2 bv = *(const float2*)(bias + col);
#pragma unroll
            for (int mi = 0; mi < 2; mi++) {
                int row = m0 + wm + (mi << 4) + g;
                float2 v0 = make_float2(c[mi][ni][0] + bv.x, c[mi][ni][1] + bv.y);
                float2 v1 = make_float2(c[mi][ni][2] + bv.x, c[mi][ni][3] + bv.y);
                *(float2*)(C + (size_t)row       * DD + col) = v0;
                *(float2*)(C + (size_t)(row + 8) * DD + col) = v1;
            }
        }
    }
}

// =============================================================================
// FP16 flash attention (causal) — R10 configuration (proven fastest):
// 128 threads / 4 warps, warp tile 32x64, ldmatrix/stmatrix fragments,
// ex2.f16x2 softmax, ones-MMA rowsum, cp.async double-buffered K/V.
// =============================================================================
#define ATT_SMEM ((128*HP + 2*64*HP + 2*64*HP + 128*HP) * 2)

__global__ __launch_bounds__(128) void flash_f16_kernel(
    const __half* __restrict__ Q, const __half* __restrict__ K,
    const __half* __restrict__ V, __half* __restrict__ O)
{
    const int qt = (SS / 128 - 1) - blockIdx.x;
    const int h  = blockIdx.y;
    const int b  = blockIdx.z;
    const int tid  = threadIdx.x;
    const int warp = tid >> 5;
    const int lane = tid & 31;
    const int g    = lane >> 2;
    const int t    = lane & 3;
    const int wm   = warp << 5;

    extern __shared__ __half smh[];
    __half* Qs = smh;                    // [128][HP]
    __half* Ks = Qs + 128 * HP;          // [2][64][HP]
    __half* Vs = Ks + 2 * 64 * HP;       // [2][64][HP]
    __half* Ps = Vs + 2 * 64 * HP;       // [128][HP]

    const uint32_t qsb = smem_u32(Qs);
    const uint32_t ksbase = smem_u32(Ks);
    const uint32_t vsbase = smem_u32(Vs);
    const uint32_t psb = smem_u32(Ps);

    const int lj = lane >> 3, lr = lane & 7;
    uint32_t moff[2], koff[4];
#pragma unroll
    for (int mi = 0; mi < 2; mi++)
        moff[mi] = (uint32_t)(((wm + (mi << 4) + ((lj & 1) << 3) + lr) * HP
                               + ((lj >> 1) << 3)) * 2);
#pragma unroll
    for (int np = 0; np < 4; np++)
        koff[np] = (uint32_t)((((np << 4) + ((lj & 1) << 3) + lr) * HP
                               + ((lj >> 1) << 3)) * 2);

    const int vrow = ((lane >> 3) & 1) * 8 + (lane & 7);
    const int vcol = (lane >> 4) * 8;

    const __half* Kh0 = K + ((size_t)(b * SS)) * DD + h * DKH;
    const __half* Vh0 = V + ((size_t)(b * SS)) * DD + h * DKH;

    auto load_kv = [&](int kt, int buf) {
        const __half* Kb = Kh0 + (size_t)(kt * 64) * DD;
        const __half* Vb = Vh0 + (size_t)(kt * 64) * DD;
        const uint32_t kb = ksbase + buf * 64 * ROWB;
        const uint32_t vb = vsbase + buf * 64 * ROWB;
#pragma unroll
        for (int i = 0; i < 4; i++) {
            int e = i * 128 + tid;
            int r = e >> 3;
            int c8 = e & 7;
            cpa16(kb + r * ROWB + (c8 << 4), Kb + (size_t)r * DD + (c8 << 3));
            cpa16(vb + r * ROWB + (c8 << 4), Vb + (size_t)r * DD + (c8 << 3));
        }
        cpa_commit();
    };

    // ---- load Q tile ----
    const __half* Qb = Q + ((size_t)(b * SS + qt * 128)) * DD + h * DKH;
#pragma unroll
    for (int i = 0; i < 8; i++) {
        int e = i * 128 + tid;
        int r = e >> 3;
        int c8 = e & 7;
        *(uint4*)&Qs[r * HP + (c8 << 3)] = *(const uint4*)(Qb + (size_t)r * DD + (c8 << 3));
    }

    load_kv(0, 0);

    float m_i[2][2], l_i[2][2], co[2][8][4];
#pragma unroll
    for (int mi = 0; mi < 2; mi++)
#pragma unroll
        for (int hh = 0; hh < 2; hh++) { m_i[mi][hh] = -INFINITY; l_i[mi][hh] = 0.f; }
#pragma unroll
    for (int mi = 0; mi < 2; mi++)
#pragma unroll
        for (int ni = 0; ni < 8; ni++)
#pragma unroll
            for (int j = 0; j < 4; j++) co[mi][ni][j] = 0.f;

    const uint32_t bones = 0x3C003C00u;  // half2(1,1)
    const int ktmax = 2 * qt + 1;

    for (int kt = 0; kt <= ktmax; kt++) {
        __syncthreads();
        if (kt < ktmax) {
            load_kv(kt + 1, (kt + 1) & 1);
            cpa_wait<1>();
        } else {
            cpa_wait<0>();
        }
        __syncthreads();

        const uint32_t ktile = ksbase + (kt & 1) * 64 * ROWB;
        const uint32_t vtile = vsbase + (kt & 1) * 64 * ROWB;

        // ---- S = Q K^T (pre-scaled via wq) ----
        float cs[2][8][4];
#pragma unroll
        for (int mi = 0; mi < 2; mi++)
#pragma unroll
            for (int ni = 0; ni < 8; ni++)
#pragma unroll
                for (int j = 0; j < 4; j++) cs[mi][ni][j] = 0.f;

#pragma unroll
        for (int ks = 0; ks < 4; ks++) {
            uint32_t a[2][4], bf[8][2];
#pragma unroll
            for (int mi = 0; mi < 2; mi++)
                ldsm4(a[mi][0], a[mi][1], a[mi][2], a[mi][3],
                      qsb + moff[mi] + ks * 32);
#pragma unroll
            for (int np = 0; np < 4; np++)
                ldsm4(bf[2*np][0], bf[2*np+1][0], bf[2*np][1], bf[2*np+1][1],
                      ktile + koff[np] + ks * 32);
#pragma unroll
            for (int mi = 0; mi < 2; mi++)
#pragma unroll
                for (int ni = 0; ni < 8; ni++)
                    mma_f16(cs[mi][ni], a[mi], bf[ni]);
        }

        // ---- causal mask (only last two tiles) ----
        if (kt >= 2 * qt) {
#pragma unroll
            for (int mi = 0; mi < 2; mi++)
#pragma unroll
                for (int ni = 0; ni < 8; ni++)
#pragma unroll
                    for (int j = 0; j < 4; j++) {
                        int row = qt * 128 + wm + (mi << 4) + g + ((j >> 1) << 3);
                        int col = kt * 64 + (ni << 3) + (t << 1) + (j & 1);
                        if (col > row) cs[mi][ni][j] = -1e9f;
                    }
        }

        // ---- online softmax: max + alpha ----
        float ml[2][2], al[2][2];
#pragma unroll
        for (int mi = 0; mi < 2; mi++)
#pragma unroll
            for (int hh = 0; hh < 2; hh++) {
                float mx = -INFINITY;
#pragma unroll
                for (int ni = 0; ni < 8; ni++)
                    mx = fmaxf(mx, fmaxf(cs[mi][ni][2*hh], cs[mi][ni][2*hh+1]));
                mx = fmaxf(mx, __shfl_xor_sync(0xffffffffu, mx, 1));
                mx = fmaxf(mx, __shfl_xor_sync(0xffffffffu, mx, 2));
                float m2 = fmaxf(m_i[mi][hh], mx);
                al[mi][hh] = __expf(m_i[mi][hh] - m2);
                m_i[mi][hh] = m2;
                ml[mi][hh] = m2 * L2E;
            }
#pragma unroll
        for (int mi = 0; mi < 2; mi++)
#pragma unroll
            for (int ni = 0; ni < 8; ni++)
#pragma unroll
                for (int j = 0; j < 4; j++)
                    co[mi][ni][j] *= al[mi][j >> 1];

        // ---- P = exp2(S*log2e - m*log2e) in half; stmatrix ----
#pragma unroll
        for (int mi = 0; mi < 2; mi++) {
#pragma unroll
            for (int np = 0; np < 4; np++) {
                int ni = 2 * np, ni1 = 2 * np + 1;
                uint32_t r0 = ex2h2(pkh2(fmaf(cs[mi][ni ][0], L2E, -ml[mi][0]),
                                         fmaf(cs[mi][ni ][1], L2E, -ml[mi][0])));
                uint32_t r1 = ex2h2(pkh2(fmaf(cs[mi][ni ][2], L2E, -ml[mi][1]),
                                         fmaf(cs[mi][ni ][3], L2E, -ml[mi][1])));
                uint32_t r2 = ex2h2(pkh2(fmaf(cs[mi][ni1][0], L2E, -ml[mi][0]),
                                         fmaf(cs[mi][ni1][1], L2E, -ml[mi][0])));
                uint32_t r3 = ex2h2(pkh2(fmaf(cs[mi][ni1][2], L2E, -ml[mi][1]),
                                         fmaf(cs[mi][ni1][3], L2E, -ml[mi][1])));
                stsm4(psb + moff[mi] + np * 32, r0, r1, r2, r3);
            }
        }
        __syncwarp();

        // ---- O += P @ V  and  l-rowsum via MMA with ones ----
        float csum[2][4];
#pragma unroll
        for (int mi = 0; mi < 2; mi++)
#pragma unroll
            for (int j = 0; j < 4; j++) csum[mi][j] = 0.f;

#pragma unroll
        for (int ks = 0; ks < 4; ks++) {
            uint32_t a[2][4], bf[8][2];
#pragma unroll
            for (int mi = 0; mi < 2; mi++)
                ldsm4(a[mi][0], a[mi][1], a[mi][2], a[mi][3],
                      psb + moff[mi] + ks * 32);
#pragma unroll
            for (int nn = 0; nn < 4; nn++) {
                uint32_t addr = vtile + ((ks << 4) + vrow) * ROWB + ((nn << 4) + vcol) * 2;
                ldsm4t(bf[2*nn][0], bf[2*nn][1], bf[2*nn+1][0], bf[2*nn+1][1], addr);
            }
#pragma unroll
            for (int mi = 0; mi < 2; mi++) {
                uint32_t bo[2] = {bones, bones};
                mma_f16(csum[mi], a[mi], bo);
#pragma unroll
                for (int ni = 0; ni < 8; ni++)
                    mma_f16(co[mi][ni], a[mi], bf[ni]);
            }
        }

#pragma unroll
        for (int mi = 0; mi < 2; mi++)
#pragma unroll
            for (int hh = 0; hh < 2; hh++)
                l_i[mi][hh] = l_i[mi][hh] * al[mi][hh] + csum[mi][2*hh];
    }

    // ---- epilogue ----
#pragma unroll
    for (int mi = 0; mi < 2; mi++)
#pragma unroll
        for (int hh = 0; hh < 2; hh++) {
            float inv = 1.f / l_i[mi][hh];
            int row = qt * 128 + wm + (mi << 4) + g + (hh << 3);
            __half* ob = O + ((size_t)(b * SS + row)) * DD + h * DKH;
#pragma unroll
            for (int ni = 0; ni < 8; ni++) {
                int col = (ni << 3) + (t << 1);
                *(uint32_t*)(ob + col) = pkh2(co[mi][ni][2*hh] * inv,
                                              co[mi][ni][2*hh+1] * inv);
            }
        }
}

// =============================================================================
// Launch
// =============================================================================
extern "C" void kernel_launch(void* const* d_in, const int* in_sizes, int n_in,
                              void* d_out, int out_size)
{
    const float* q  = (const float*)d_in[1];
    const float* k  = (const float*)d_in[2];
    const float* v  = (const float*)d_in[3];
    const float* wq = (const float*)d_in[5];
    const float* bq = (const float*)d_in[6];
    const float* wk = (const float*)d_in[7];
    const float* bk = (const float*)d_in[8];
    const float* wv = (const float*)d_in[9];
    const float* bv = (const float*)d_in[10];
    const float* wo = (const float*)d_in[11];
    const float* bo = (const float*)d_in[12];
    float* out = (float*)d_out;

    __half *aq, *ak, *av, *qh, *kh, *vh, *aoh, *wtq, *wtk, *wtv, *wto;
    cudaGetSymbolAddress((void**)&aq,  g_Aq);
    cudaGetSymbolAddress((void**)&ak,  g_Ak);
    cudaGetSymbolAddress((void**)&av,  g_Av);
    cudaGetSymbolAddress((void**)&qh,  g_Qh);
    cudaGetSymbolAddress((void**)&kh,  g_Kh);
    cudaGetSymbolAddress((void**)&vh,  g_Vh);
    cudaGetSymbolAddress((void**)&aoh, g_AOh);
    cudaGetSymbolAddress((void**)&wtq, g_Wq);
    cudaGetSymbolAddress((void**)&wtk, g_Wk);
    cudaGetSymbolAddress((void**)&wtv, g_Wv);
    cudaGetSymbolAddress((void**)&wto, g_Wo);

    cudaFuncSetAttribute(flash_f16_kernel,
                         cudaFuncAttributeMaxDynamicSharedMemorySize, ATT_SMEM);
    cudaFuncSetAttribute(gemm_qkv_f16,
                         cudaFuncAttributeMaxDynamicSharedMemorySize, G_SMEM);
    cudaFuncSetAttribute(gemm_o_f16,
                         cudaFuncAttributeMaxDynamicSharedMemorySize, G_SMEM);

    // ---- prepass (2 launches) ----
    const int nA4 = MTOT * DD / 4;
    act_conv_kernel<<<dim3(nA4 / 256, 3), 256>>>(q, k, v, aq, ak, av);
    wt_trans_kernel<<<dim3(DD / 32, DD / 32, 4), dim3(32, 8)>>>(
        wq, wk, wv, wo, wtq, wtk, wtv, wto);

    // ---- fused QKV projections (persistent, 296 CTAs) ----
    gemm_qkv_f16<<<PGRID, 256, G_SMEM>>>(aq, ak, av, wtq, wtk, wtv,
                                         bq, bk, bv, qh, kh, vh);

    // ---- attention (R10 config: 128 threads) ----
    dim3 agrid(SS / 128, HH, BB);         // (16, 16, 4)
    flash_f16_kernel<<<agrid, dim3(128), ATT_SMEM>>>(qh, kh, vh, aoh);

    // ---- output projection (persistent, 296 CTAs, fp32 out) ----
    gemm_o_f16<<<PGRID, 256, G_SMEM>>>(aoh, wto, bo, out);
}

// round 13
// speedup vs baseline: 1.0126x; 1.0039x over previous
#include <cuda_runtime.h>
#include <cuda_fp16.h>
#include <math.h>
#include <stdint.h>

// Problem constants
#define BB 4
#define SS 2048
#define DD 1024
#define HH 16
#define DKH 64
#define MTOT (BB*SS)          // 8192 rows

#define L2E 1.4426950408889634f

// ---------------- scratch (static device globals; no allocation) -------------
__device__ __half g_Aq[MTOT*DD];
__device__ __half g_Ak[MTOT*DD];
__device__ __half g_Av[MTOT*DD];
__device__ __half g_Qh[MTOT*DD];
__device__ __half g_Kh[MTOT*DD];
__device__ __half g_Vh[MTOT*DD];
__device__ __half g_AOh[MTOT*DD];
__device__ __half g_Wq[DD*DD];     // WT[n][k] half (wq pre-scaled by 0.125)
__device__ __half g_Wk[DD*DD];
__device__ __half g_Wv[DD*DD];
__device__ __half g_Wo[DD*DD];

// ---------------- helpers -----------------------------------------------------
__device__ __forceinline__ uint32_t pkh2(float a, float b) {
    __half2 h = __floats2half2_rn(a, b);
    return *(uint32_t*)&h;
}
__device__ __forceinline__ uint32_t ex2h2(uint32_t x) {
    uint32_t r;
    asm("ex2.approx.f16x2 %0, %1;" : "=r"(r) : "r"(x));
    return r;
}
__device__ __forceinline__ void cpa16(uint32_t smem, const void* gmem) {
    asm volatile("cp.async.cg.shared.global [%0], [%1], 16;" :: "r"(smem), "l"(gmem));
}
__device__ __forceinline__ void cpa_commit() {
    asm volatile("cp.async.commit_group;");
}
template<int N> __device__ __forceinline__ void cpa_wait() {
    asm volatile("cp.async.wait_group %0;" :: "n"(N));
}
__device__ __forceinline__ uint32_t smem_u32(const void* p) {
    uint32_t a;
    asm("{ .reg .u64 t; cvta.to.shared.u64 t, %1; cvt.u32.u64 %0, t; }"
        : "=r"(a) : "l"(p));
    return a;
}
__device__ __forceinline__ void mma_f16(
    float c[4], const uint32_t a[4], const uint32_t b[2])
{
    asm volatile(
        "mma.sync.aligned.m16n8k16.row.col.f32.f16.f16.f32 "
        "{%0,%1,%2,%3}, {%4,%5,%6,%7}, {%8,%9}, {%0,%1,%2,%3};"
        : "+f"(c[0]), "+f"(c[1]), "+f"(c[2]), "+f"(c[3])
        : "r"(a[0]), "r"(a[1]), "r"(a[2]), "r"(a[3]),
          "r"(b[0]), "r"(b[1]));
}
__device__ __forceinline__ void ldsm4(
    uint32_t& r0, uint32_t& r1, uint32_t& r2, uint32_t& r3, uint32_t a)
{
    asm volatile("ldmatrix.sync.aligned.m8n8.x4.shared.b16 {%0,%1,%2,%3}, [%4];"
                 : "=r"(r0), "=r"(r1), "=r"(r2), "=r"(r3) : "r"(a));
}
__device__ __forceinline__ void ldsm4t(
    uint32_t& r0, uint32_t& r1, uint32_t& r2, uint32_t& r3, uint32_t a)
{
    asm volatile("ldmatrix.sync.aligned.m8n8.x4.trans.shared.b16 {%0,%1,%2,%3}, [%4];"
                 : "=r"(r0), "=r"(r1), "=r"(r2), "=r"(r3) : "r"(a));
}
__device__ __forceinline__ void stsm4(
    uint32_t a, uint32_t r0, uint32_t r1, uint32_t r2, uint32_t r3)
{
    asm volatile("stmatrix.sync.aligned.m8n8.x4.shared.b16 [%0], {%1,%2,%3,%4};"
                 :: "r"(a), "r"(r0), "r"(r1), "r"(r2), "r"(r3) : "memory");
}

// ---------------- prepass kernels (merged) ------------------------------------
__global__ __launch_bounds__(256) void act_conv_kernel(
    const float* __restrict__ q, const float* __restrict__ k,
    const float* __restrict__ v,
    __half* __restrict__ oq, __half* __restrict__ ok, __half* __restrict__ ov)
{
    const int which = blockIdx.y;
    const float* in = (which == 0) ? q : (which == 1) ? k : v;
    __half* out     = (which == 0) ? oq : (which == 1) ? ok : ov;
    int i = blockIdx.x * blockDim.x + threadIdx.x;
    float4 vv = ((const float4*)in)[i];
    uint2 o;
    o.x = pkh2(vv.x, vv.y);
    o.y = pkh2(vv.z, vv.w);
    ((uint2*)out)[i] = o;
}

// WT[n][k] = half(W[k][n] * scale); wq gets scale 0.125
__global__ __launch_bounds__(256) void wt_trans_kernel(
    const float* __restrict__ wq, const float* __restrict__ wk,
    const float* __restrict__ wv, const float* __restrict__ wo,
    __half* __restrict__ oq, __half* __restrict__ ok,
    __half* __restrict__ ov, __half* __restrict__ oo)
{
    const int which = blockIdx.z;
    const float* in = (which == 0) ? wq : (which == 1) ? wk : (which == 2) ? wv : wo;
    __half* out     = (which == 0) ? oq : (which == 1) ? ok : (which == 2) ? ov : oo;
    const float sc  = (which == 0) ? 0.125f : 1.0f;

    __shared__ float tl[32][33];
    const int tx = threadIdx.x, ty = threadIdx.y;
    const int n0 = blockIdx.x * 32, k0 = blockIdx.y * 32;
#pragma unroll
    for (int i = 0; i < 4; i++)
        tl[ty + i * 8][tx] = in[(size_t)(k0 + ty + i * 8) * DD + n0 + tx];
    __syncthreads();
#pragma unroll
    for (int i = 0; i < 4; i++)
        out[(size_t)(n0 + ty + i * 8) * DD + k0 + tx] =
            __float2half(tl[tx][ty + i * 8] * sc);
}

// =============================================================================
// Persistent continuous-pipeline FP16 HMMA GEMM (fused QKV): 296 CTAs,
// 1536 tiles, single cp.async stream across tile boundaries (never drains).
// Block tile 128x128, K-tile 64, ldmatrix fragments, 3-stage ring.
// =============================================================================
#define HP 72
#define ROWB (HP*2)                       // 144 bytes per smem row
#define G_STG_H (2 * 128 * HP)
#define G_SMEM (3 * G_STG_H * 2)          // 110592 bytes
#define PGRID 296                         // 2 CTAs/SM * 148 SMs

__global__ __launch_bounds__(256) void gemm_qkv_f16(
    const __half* __restrict__ A0, const __half* __restrict__ A1,
    const __half* __restrict__ A2,
    const __half* __restrict__ W0, const __half* __restrict__ W1,
    const __half* __restrict__ W2,
    const float* __restrict__ b0, const float* __restrict__ b1,
    const float* __restrict__ b2,
    __half* __restrict__ C0, __half* __restrict__ C1, __half* __restrict__ C2)
{
    extern __shared__ __half shh[];

    const int tid  = threadIdx.x;
    const int wid  = tid >> 5;
    const int lane = tid & 31;
    const int g    = lane >> 2;
    const int t    = lane & 3;
    const int wm   = (wid & 3) << 5;
    const int wn   = (wid >> 2) << 6;

    const int lj = lane >> 3, lr = lane & 7;
    uint32_t aoff[2], boff[4];
#pragma unroll
    for (int mi = 0; mi < 2; mi++)
        aoff[mi] = (uint32_t)(((wm + (mi << 4) + ((lj & 1) << 3) + lr) * HP
                               + ((lj >> 1) << 3)) * 2);
#pragma unroll
    for (int np = 0; np < 4; np++)
        boff[np] = (uint32_t)(((wn + (np << 4) + ((lj & 1) << 3) + lr) * HP
                               + ((lj >> 1) << 3)) * 2);

    const uint32_t shbase = smem_u32(shh);

    const int ntiles = (1536 - 1 - (int)blockIdx.x) / PGRID + 1;
    const int total  = ntiles << 4;          // k-iterations overall

    // prefetch one k-iteration (gi) into stage gi%3
    auto prefetch = [&](int gi) {
        const int ti  = gi >> 4;
        const int kt  = gi & 15;
        const int idx = (int)blockIdx.x + ti * PGRID;
        const int z   = idx >> 9;
        const int rem = idx & 511;
        const int m0  = (rem >> 3) << 7;
        const int n0  = (rem & 7) << 7;
        const __half* A  = (z == 0) ? A0 : (z == 1) ? A1 : A2;
        const __half* WT = (z == 0) ? W0 : (z == 1) ? W1 : W2;
        const int k0 = kt << 6;
        const int stg = gi % 3;
        const uint32_t sa = shbase + (stg * G_STG_H) * 2;
        const uint32_t sb = sa + 128 * ROWB;
#pragma unroll
        for (int j = 0; j < 4; j++) {
            int ca = j * 256 + tid;
            int row = ca >> 3, k8 = ca & 7;
            cpa16(sa + row * ROWB + (k8 << 4),
                  A + (size_t)(m0 + row) * DD + k0 + (k8 << 3));
        }
#pragma unroll
        for (int j = 0; j < 4; j++) {
            int cb = j * 256 + tid;
            int row = cb >> 3, k8 = cb & 7;
            cpa16(sb + row * ROWB + (k8 << 4),
                  WT + (size_t)(n0 + row) * DD + k0 + (k8 << 3));
        }
        cpa_commit();
    };

    prefetch(0);
    prefetch(1);

    float c[2][8][4];
    int cm0 = 0, cn0 = 0;
    const float* cbias = b0;
    __half* cC = C0;
    float cbsc = 1.f;

    for (int gi = 0; gi < total; gi++) {
        const int kt = gi & 15;
        if (kt == 0) {
            const int idx = (int)blockIdx.x + (gi >> 4) * PGRID;
            const int z   = idx >> 9;
            const int rem = idx & 511;
            cm0 = (rem >> 3) << 7;
            cn0 = (rem & 7) << 7;
            cbias = (z == 0) ? b0 : (z == 1) ? b1 : b2;
            cC    = (z == 0) ? C0 : (z == 1) ? C1 : C2;
            cbsc  = (z == 0) ? 0.125f : 1.0f;
#pragma unroll
            for (int mi = 0; mi < 2; mi++)
#pragma unroll
                for (int ni = 0; ni < 8; ni++)
#pragma unroll
                    for (int j = 0; j < 4; j++) c[mi][ni][j] = 0.f;
        }

        if (gi + 1 < total) cpa_wait<1>(); else cpa_wait<0>();
        __syncthreads();
        if (gi + 2 < total) prefetch(gi + 2);

        const int stg = gi % 3;
        const uint32_t sa = shbase + (stg * G_STG_H) * 2;
        const uint32_t sb = sa + 128 * ROWB;

#pragma unroll
        for (int ks = 0; ks < 4; ks++) {
            uint32_t a[2][4], b[8][2];
#pragma unroll
            for (int mi = 0; mi < 2; mi++)
                ldsm4(a[mi][0], a[mi][1], a[mi][2], a[mi][3],
                      sa + aoff[mi] + ks * 32);
#pragma unroll
            for (int np = 0; np < 4; np++)
                ldsm4(b[2*np][0], b[2*np+1][0], b[2*np][1], b[2*np+1][1],
                      sb + boff[np] + ks * 32);
#pragma unroll
            for (int mi = 0; mi < 2; mi++)
#pragma unroll
                for (int ni = 0; ni < 8; ni++)
                    mma_f16(c[mi][ni], a[mi], b[ni]);
        }

        if (kt == 15) {
#pragma unroll
            for (int ni = 0; ni < 8; ni++) {
                int col = cn0 + wn + (ni << 3) + (t << 1);
                float2 bv = *(const float2*)(cbias + col);
                bv.x *= cbsc; bv.y *= cbsc;
#pragma unroll
                for (int mi = 0; mi < 2; mi++) {
                    int row = cm0 + wm + (mi << 4) + g;
                    *(uint32_t*)(cC + (size_t)row       * DD + col) =
                        pkh2(c[mi][ni][0] + bv.x, c[mi][ni][1] + bv.y);
                    *(uint32_t*)(cC + (size_t)(row + 8) * DD + col) =
                        pkh2(c[mi][ni][2] + bv.x, c[mi][ni][3] + bv.y);
                }
            }
        }
    }
}

// Persistent continuous-pipeline single GEMM (output projection, fp32 out).
__global__ __launch_bounds__(256) void gemm_o_f16(
    const __half* __restrict__ A, const __half* __restrict__ WT,
    const float* __restrict__ bias, float* __restrict__ C)
{
    extern __shared__ __half shh[];

    const int tid  = threadIdx.x;
    const int wid  = tid >> 5;
    const int lane = tid & 31;
    const int g    = lane >> 2;
    const int t    = lane & 3;
    const int wm   = (wid & 3) << 5;
    const int wn   = (wid >> 2) << 6;

    const int lj = lane >> 3, lr = lane & 7;
    uint32_t aoff[2], boff[4];
#pragma unroll
    for (int mi = 0; mi < 2; mi++)
        aoff[mi] = (uint32_t)(((wm + (mi << 4) + ((lj & 1) << 3) + lr) * HP
                               + ((lj >> 1) << 3)) * 2);
#pragma unroll
    for (int np = 0; np < 4; np++)
        boff[np] = (uint32_t)(((wn + (np << 4) + ((lj & 1) << 3) + lr) * HP
                               + ((lj >> 1) << 3)) * 2);

    const uint32_t shbase = smem_u32(shh);

    if ((int)blockIdx.x >= 512) return;
    const int ntiles = (512 - 1 - (int)blockIdx.x) / PGRID + 1;
    const int total  = ntiles << 4;

    auto prefetch = [&](int gi) {
        const int ti  = gi >> 4;
        const int kt  = gi & 15;
        const int idx = (int)blockIdx.x + ti * PGRID;
        const int m0  = (idx >> 3) << 7;
        const int n0  = (idx & 7) << 7;
        const int k0 = kt << 6;
        const int stg = gi % 3;
        const uint32_t sa = shbase + (stg * G_STG_H) * 2;
        const uint32_t sb = sa + 128 * ROWB;
#pragma unroll
        for (int j = 0; j < 4; j++) {
            int ca = j * 256 + tid;
            int row = ca >> 3, k8 = ca & 7;
            cpa16(sa + row * ROWB + (k8 << 4),
                  A + (size_t)(m0 + row) * DD + k0 + (k8 << 3));
        }
#pragma unroll
        for (int j = 0; j < 4; j++) {
            int cb = j * 256 + tid;
            int row = cb >> 3, k8 = cb & 7;
            cpa16(sb + row * ROWB + (k8 << 4),
                  WT + (size_t)(n0 + row) * DD + k0 + (k8 << 3));
        }
        cpa_commit();
    };

    prefetch(0);
    if (total > 1) prefetch(1);

    float c[2][8][4];
    int cm0 = 0, cn0 = 0;

    for (int gi = 0; gi < total; gi++) {
        const int kt = gi & 15;
        if (kt == 0) {
            const int idx = (int)blockIdx.x + (gi >> 4) * PGRID;
            cm0 = (idx >> 3) << 7;
            cn0 = (idx & 7) << 7;
#pragma unroll
            for (int mi = 0; mi < 2; mi++)
#pragma unroll
                for (int ni = 0; ni < 8; ni++)
#pragma unroll
                    for (int j = 0; j < 4; j++) c[mi][ni][j] = 0.f;
        }

        if (gi + 1 < total) cpa_wait<1>(); else cpa_wait<0>();
        __syncthreads();
        if (gi + 2 < total) prefetch(gi + 2);

        const int stg = gi % 3;
        const uint32_t sa = shbase + (stg * G_STG_H) * 2;
        const uint32_t sb = sa + 128 * ROWB;

#pragma unroll
        for (int ks = 0; ks < 4; ks++) {
            uint32_t a[2][4], b[8][2];
#pragma unroll
            for (int mi = 0; mi < 2; mi++)
                ldsm4(a[mi][0], a[mi][1], a[mi][2], a[mi][3],
                      sa + aoff[mi] + ks * 32);
#pragma unroll
            for (int np = 0; np < 4; np++)
                ldsm4(b[2*np][0], b[2*np+1][0], b[2*np][1], b[2*np+1][1],
                      sb + boff[np] + ks * 32);
#pragma unroll
            for (int mi = 0; mi < 2; mi++)
#pragma unroll
                for (int ni = 0; ni < 8; ni++)
                    mma_f16(c[mi][ni], a[mi], b[ni]);
        }

        if (kt == 15) {
#pragma unroll
            for (int ni = 0; ni < 8; ni++) {
                int col = cn0 + wn + (ni << 3) + (t << 1);
                float2 bv = *(const float2*)(bias + col);
#pragma unroll
                for (int mi = 0; mi < 2; mi++) {
                    int row = cm0 + wm + (mi << 4) + g;
                    float2 v0 = make_float2(c[mi][ni][0] + bv.x, c[mi][ni][1] + bv.y);
                    float2 v1 = make_float2(c[mi][ni][2] + bv.x, c[mi][ni][3] + bv.y);
                    *(float2*)(C + (size_t)row       * DD + col) = v0;
                    *(float2*)(C + (size_t)(row + 8) * DD + col) = v1;
                }
            }
        }
    }
}

// =============================================================================
// FP16 flash attention (causal) — R10 configuration (proven fastest):
// 128 threads / 4 warps, warp tile 32x64, ldmatrix/stmatrix fragments,
// ex2.f16x2 softmax, ones-MMA rowsum, cp.async double-buffered K/V.
// =============================================================================
#define ATT_SMEM ((128*HP + 2*64*HP + 2*64*HP + 128*HP) * 2)

__global__ __launch_bounds__(128) void flash_f16_kernel(
    const __half* __restrict__ Q, const __half* __restrict__ K,
    const __half* __restrict__ V, __half* __restrict__ O)
{
    const int qt = (SS / 128 - 1) - blockIdx.x;
    const int h  = blockIdx.y;
    const int b  = blockIdx.z;
    const int tid  = threadIdx.x;
    const int warp = tid >> 5;
    const int lane = tid & 31;
    const int g    = lane >> 2;
    const int t    = lane & 3;
    const int wm   = warp << 5;

    extern __shared__ __half smh[];
    __half* Qs = smh;                    // [128][HP]
    __half* Ks = Qs + 128 * HP;          // [2][64][HP]
    __half* Vs = Ks + 2 * 64 * HP;       // [2][64][HP]
    __half* Ps = Vs + 2 * 64 * HP;       // [128][HP]

    const uint32_t qsb = smem_u32(Qs);
    const uint32_t ksbase = smem_u32(Ks);
    const uint32_t vsbase = smem_u32(Vs);
    const uint32_t psb = smem_u32(Ps);

    const int lj = lane >> 3, lr = lane & 7;
    uint32_t moff[2], koff[4];
#pragma unroll
    for (int mi = 0; mi < 2; mi++)
        moff[mi] = (uint32_t)(((wm + (mi << 4) + ((lj & 1) << 3) + lr) * HP
                               + ((lj >> 1) << 3)) * 2);
#pragma unroll
    for (int np = 0; np < 4; np++)
        koff[np] = (uint32_t)((((np << 4) + ((lj & 1) << 3) + lr) * HP
                               + ((lj >> 1) << 3)) * 2);

    const int vrow = ((lane >> 3) & 1) * 8 + (lane & 7);
    const int vcol = (lane >> 4) * 8;

    const __half* Kh0 = K + ((size_t)(b * SS)) * DD + h * DKH;
    const __half* Vh0 = V + ((size_t)(b * SS)) * DD + h * DKH;

    auto load_kv = [&](int kt, int buf) {
        const __half* Kb = Kh0 + (size_t)(kt * 64) * DD;
        const __half* Vb = Vh0 + (size_t)(kt * 64) * DD;
        const uint32_t kb = ksbase + buf * 64 * ROWB;
        const uint32_t vb = vsbase + buf * 64 * ROWB;
#pragma unroll
        for (int i = 0; i < 4; i++) {
            int e = i * 128 + tid;
            int r = e >> 3;
            int c8 = e & 7;
            cpa16(kb + r * ROWB + (c8 << 4), Kb + (size_t)r * DD + (c8 << 3));
            cpa16(vb + r * ROWB + (c8 << 4), Vb + (size_t)r * DD + (c8 << 3));
        }
        cpa_commit();
    };

    // ---- load Q tile ----
    const __half* Qb = Q + ((size_t)(b * SS + qt * 128)) * DD + h * DKH;
#pragma unroll
    for (int i = 0; i < 8; i++) {
        int e = i * 128 + tid;
        int r = e >> 3;
        int c8 = e & 7;
        *(uint4*)&Qs[r * HP + (c8 << 3)] = *(const uint4*)(Qb + (size_t)r * DD + (c8 << 3));
    }

    load_kv(0, 0);

    float m_i[2][2], l_i[2][2], co[2][8][4];
#pragma unroll
    for (int mi = 0; mi < 2; mi++)
#pragma unroll
        for (int hh = 0; hh < 2; hh++) { m_i[mi][hh] = -INFINITY; l_i[mi][hh] = 0.f; }
#pragma unroll
    for (int mi = 0; mi < 2; mi++)
#pragma unroll
        for (int ni = 0; ni < 8; ni++)
#pragma unroll
            for (int j = 0; j < 4; j++) co[mi][ni][j] = 0.f;

    const uint32_t bones = 0x3C003C00u;  // half2(1,1)
    const int ktmax = 2 * qt + 1;

    for (int kt = 0; kt <= ktmax; kt++) {
        __syncthreads();
        if (kt < ktmax) {
            load_kv(kt + 1, (kt + 1) & 1);
            cpa_wait<1>();
        } else {
            cpa_wait<0>();
        }
        __syncthreads();

        const uint32_t ktile = ksbase + (kt & 1) * 64 * ROWB;
        const uint32_t vtile = vsbase + (kt & 1) * 64 * ROWB;

        // ---- S = Q K^T (pre-scaled via wq) ----
        float cs[2][8][4];
#pragma unroll
        for (int mi = 0; mi < 2; mi++)
#pragma unroll
            for (int ni = 0; ni < 8; ni++)
#pragma unroll
                for (int j = 0; j < 4; j++) cs[mi][ni][j] = 0.f;

#pragma unroll
        for (int ks = 0; ks < 4; ks++) {
            uint32_t a[2][4], bf[8][2];
#pragma unroll
            for (int mi = 0; mi < 2; mi++)
                ldsm4(a[mi][0], a[mi][1], a[mi][2], a[mi][3],
                      qsb + moff[mi] + ks * 32);
#pragma unroll
            for (int np = 0; np < 4; np++)
                ldsm4(bf[2*np][0], bf[2*np+1][0], bf[2*np][1], bf[2*np+1][1],
                      ktile + koff[np] + ks * 32);
#pragma unroll
            for (int mi = 0; mi < 2; mi++)
#pragma unroll
                for (int ni = 0; ni < 8; ni++)
                    mma_f16(cs[mi][ni], a[mi], bf[ni]);
        }

        // ---- causal mask (only last two tiles) ----
        if (kt >= 2 * qt) {
#pragma unroll
            for (int mi = 0; mi < 2; mi++)
#pragma unroll
                for (int ni = 0; ni < 8; ni++)
#pragma unroll
                    for (int j = 0; j < 4; j++) {
                        int row = qt * 128 + wm + (mi << 4) + g + ((j >> 1) << 3);
                        int col = kt * 64 + (ni << 3) + (t << 1) + (j & 1);
                        if (col > row) cs[mi][ni][j] = -1e9f;
                    }
        }

        // ---- online softmax: max + alpha ----
        float ml[2][2], al[2][2];
#pragma unroll
        for (int mi = 0; mi < 2; mi++)
#pragma unroll
            for (int hh = 0; hh < 2; hh++) {
                float mx = -INFINITY;
#pragma unroll
                for (int ni = 0; ni < 8; ni++)
                    mx = fmaxf(mx, fmaxf(cs[mi][ni][2*hh], cs[mi][ni][2*hh+1]));
                mx = fmaxf(mx, __shfl_xor_sync(0xffffffffu, mx, 1));
                mx = fmaxf(mx, __shfl_xor_sync(0xffffffffu, mx, 2));
                float m2 = fmaxf(m_i[mi][hh], mx);
                al[mi][hh] = __expf(m_i[mi][hh] - m2);
                m_i[mi][hh] = m2;
                ml[mi][hh] = m2 * L2E;
            }
#pragma unroll
        for (int mi = 0; mi < 2; mi++)
#pragma unroll
            for (int ni = 0; ni < 8; ni++)
#pragma unroll
                for (int j = 0; j < 4; j++)
                    co[mi][ni][j] *= al[mi][j >> 1];

        // ---- P = exp2(S*log2e - m*log2e) in half; stmatrix ----
#pragma unroll
        for (int mi = 0; mi < 2; mi++) {
#pragma unroll
            for (int np = 0; np < 4; np++) {
                int ni = 2 * np, ni1 = 2 * np + 1;
                uint32_t r0 = ex2h2(pkh2(fmaf(cs[mi][ni ][0], L2E, -ml[mi][0]),
                                         fmaf(cs[mi][ni ][1], L2E, -ml[mi][0])));
                uint32_t r1 = ex2h2(pkh2(fmaf(cs[mi][ni ][2], L2E, -ml[mi][1]),
                                         fmaf(cs[mi][ni ][3], L2E, -ml[mi][1])));
                uint32_t r2 = ex2h2(pkh2(fmaf(cs[mi][ni1][0], L2E, -ml[mi][0]),
                                         fmaf(cs[mi][ni1][1], L2E, -ml[mi][0])));
                uint32_t r3 = ex2h2(pkh2(fmaf(cs[mi][ni1][2], L2E, -ml[mi][1]),
                                         fmaf(cs[mi][ni1][3], L2E, -ml[mi][1])));
                stsm4(psb + moff[mi] + np * 32, r0, r1, r2, r3);
            }
        }
        __syncwarp();

        // ---- O += P @ V  and  l-rowsum via MMA with ones ----
        float csum[2][4];
#pragma unroll
        for (int mi = 0; mi < 2; mi++)
#pragma unroll
            for (int j = 0; j < 4; j++) csum[mi][j] = 0.f;

#pragma unroll
        for (int ks = 0; ks < 4; ks++) {
            uint32_t a[2][4], bf[8][2];
#pragma unroll
            for (int mi = 0; mi < 2; mi++)
                ldsm4(a[mi][0], a[mi][1], a[mi][2], a[mi][3],
                      psb + moff[mi] + ks * 32);
#pragma unroll
            for (int nn = 0; nn < 4; nn++) {
                uint32_t addr = vtile + ((ks << 4) + vrow) * ROWB + ((nn << 4) + vcol) * 2;
                ldsm4t(bf[2*nn][0], bf[2*nn][1], bf[2*nn+1][0], bf[2*nn+1][1], addr);
            }
#pragma unroll
            for (int mi = 0; mi < 2; mi++) {
                uint32_t bo[2] = {bones, bones};
                mma_f16(csum[mi], a[mi], bo);
#pragma unroll
                for (int ni = 0; ni < 8; ni++)
                    mma_f16(co[mi][ni], a[mi], bf[ni]);
            }
        }

#pragma unroll
        for (int mi = 0; mi < 2; mi++)
#pragma unroll
            for (int hh = 0; hh < 2; hh++)
                l_i[mi][hh] = l_i[mi][hh] * al[mi][hh] + csum[mi][2*hh];
    }

    // ---- epilogue ----
#pragma unroll
    for (int mi = 0; mi < 2; mi++)
#pragma unroll
        for (int hh = 0; hh < 2; hh++) {
            float inv = 1.f / l_i[mi][hh];
            int row = qt * 128 + wm + (mi << 4) + g + (hh << 3);
            __half* ob = O + ((size_t)(b * SS + row)) * DD + h * DKH;
#pragma unroll
            for (int ni = 0; ni < 8; ni++) {
                int col = (ni << 3) + (t << 1);
                *(uint32_t*)(ob + col) = pkh2(co[mi][ni][2*hh] * inv,
                                              co[mi][ni][2*hh+1] * inv);
            }
        }
}

// =============================================================================
// Launch
// =============================================================================
extern "C" void kernel_launch(void* const* d_in, const int* in_sizes, int n_in,
                              void* d_out, int out_size)
{
    const float* q  = (const float*)d_in[1];
    const float* k  = (const float*)d_in[2];
    const float* v  = (const float*)d_in[3];
    const float* wq = (const float*)d_in[5];
    const float* bq = (const float*)d_in[6];
    const float* wk = (const float*)d_in[7];
    const float* bk = (const float*)d_in[8];
    const float* wv = (const float*)d_in[9];
    const float* bv = (const float*)d_in[10];
    const float* wo = (const float*)d_in[11];
    const float* bo = (const float*)d_in[12];
    float* out = (float*)d_out;

    __half *aq, *ak, *av, *qh, *kh, *vh, *aoh, *wtq, *wtk, *wtv, *wto;
    cudaGetSymbolAddress((void**)&aq,  g_Aq);
    cudaGetSymbolAddress((void**)&ak,  g_Ak);
    cudaGetSymbolAddress((void**)&av,  g_Av);
    cudaGetSymbolAddress((void**)&qh,  g_Qh);
    cudaGetSymbolAddress((void**)&kh,  g_Kh);
    cudaGetSymbolAddress((void**)&vh,  g_Vh);
    cudaGetSymbolAddress((void**)&aoh, g_AOh);
    cudaGetSymbolAddress((void**)&wtq, g_Wq);
    cudaGetSymbolAddress((void**)&wtk, g_Wk);
    cudaGetSymbolAddress((void**)&wtv, g_Wv);
    cudaGetSymbolAddress((void**)&wto, g_Wo);

    cudaFuncSetAttribute(flash_f16_kernel,
                         cudaFuncAttributeMaxDynamicSharedMemorySize, ATT_SMEM);
    cudaFuncSetAttribute(gemm_qkv_f16,
                         cudaFuncAttributeMaxDynamicSharedMemorySize, G_SMEM);
    cudaFuncSetAttribute(gemm_o_f16,
                         cudaFuncAttributeMaxDynamicSharedMemorySize, G_SMEM);

    // ---- prepass (2 launches) ----
    const int nA4 = MTOT * DD / 4;
    act_conv_kernel<<<dim3(nA4 / 256, 3), 256>>>(q, k, v, aq, ak, av);
    wt_trans_kernel<<<dim3(DD / 32, DD / 32, 4), dim3(32, 8)>>>(
        wq, wk, wv, wo, wtq, wtk, wtv, wto);

    // ---- fused QKV projections (persistent, continuous pipeline) ----
    gemm_qkv_f16<<<PGRID, 256, G_SMEM>>>(aq, ak, av, wtq, wtk, wtv,
                                         bq, bk, bv, qh, kh, vh);

    // ---- attention (R10 config: 128 threads) ----
    dim3 agrid(SS / 128, HH, BB);         // (16, 16, 4)
    flash_f16_kernel<<<agrid, dim3(128), ATT_SMEM>>>(qh, kh, vh, aoh);

    // ---- output projection (persistent, continuous pipeline, fp32 out) ----
    gemm_o_f16<<<PGRID, 256, G_SMEM>>>(aoh, wto, bo, out);
}

// round 14
// speedup vs baseline: 1.0180x; 1.0053x over previous
#include <cuda_runtime.h>
#include <cuda_fp16.h>
#include <math.h>
#include <stdint.h>

// Problem constants
#define BB 4
#define SS 2048
#define DD 1024
#define HH 16
#define DKH 64
#define MTOT (BB*SS)          // 8192 rows

#define L2E 1.4426950408889634f

// ---------------- scratch (static device globals; no allocation) -------------
__device__ __half g_Aq[MTOT*DD];
__device__ __half g_Ak[MTOT*DD];
__device__ __half g_Av[MTOT*DD];
__device__ __half g_Qh[MTOT*DD];
__device__ __half g_Kh[MTOT*DD];
__device__ __half g_Vh[MTOT*DD];
__device__ __half g_AOh[MTOT*DD];
__device__ __half g_Wq[DD*DD];     // WT[n][k] half (wq pre-scaled by 0.125)
__device__ __half g_Wk[DD*DD];
__device__ __half g_Wv[DD*DD];
__device__ __half g_Wo[DD*DD];

// ---------------- helpers -----------------------------------------------------
__device__ __forceinline__ uint32_t pkh2(float a, float b) {
    __half2 h = __floats2half2_rn(a, b);
    return *(uint32_t*)&h;
}
__device__ __forceinline__ uint32_t ex2h2(uint32_t x) {
    uint32_t r;
    asm("ex2.approx.f16x2 %0, %1;" : "=r"(r) : "r"(x));
    return r;
}
__device__ __forceinline__ void cpa16(uint32_t smem, const void* gmem) {
    asm volatile("cp.async.cg.shared.global [%0], [%1], 16;" :: "r"(smem), "l"(gmem));
}
__device__ __forceinline__ void cpa_commit() {
    asm volatile("cp.async.commit_group;");
}
template<int N> __device__ __forceinline__ void cpa_wait() {
    asm volatile("cp.async.wait_group %0;" :: "n"(N));
}
__device__ __forceinline__ uint32_t smem_u32(const void* p) {
    uint32_t a;
    asm("{ .reg .u64 t; cvta.to.shared.u64 t, %1; cvt.u32.u64 %0, t; }"
        : "=r"(a) : "l"(p));
    return a;
}
__device__ __forceinline__ void mma_f16(
    float c[4], const uint32_t a[4], const uint32_t b[2])
{
    asm volatile(
        "mma.sync.aligned.m16n8k16.row.col.f32.f16.f16.f32 "
        "{%0,%1,%2,%3}, {%4,%5,%6,%7}, {%8,%9}, {%0,%1,%2,%3};"
        : "+f"(c[0]), "+f"(c[1]), "+f"(c[2]), "+f"(c[3])
        : "r"(a[0]), "r"(a[1]), "r"(a[2]), "r"(a[3]),
          "r"(b[0]), "r"(b[1]));
}
__device__ __forceinline__ void ldsm4(
    uint32_t& r0, uint32_t& r1, uint32_t& r2, uint32_t& r3, uint32_t a)
{
    asm volatile("ldmatrix.sync.aligned.m8n8.x4.shared.b16 {%0,%1,%2,%3}, [%4];"
                 : "=r"(r0), "=r"(r1), "=r"(r2), "=r"(r3) : "r"(a));
}
__device__ __forceinline__ void ldsm4t(
    uint32_t& r0, uint32_t& r1, uint32_t& r2, uint32_t& r3, uint32_t a)
{
    asm volatile("ldmatrix.sync.aligned.m8n8.x4.trans.shared.b16 {%0,%1,%2,%3}, [%4];"
                 : "=r"(r0), "=r"(r1), "=r"(r2), "=r"(r3) : "r"(a));
}
__device__ __forceinline__ void stsm4(
    uint32_t a, uint32_t r0, uint32_t r1, uint32_t r2, uint32_t r3)
{
    asm volatile("stmatrix.sync.aligned.m8n8.x4.shared.b16 [%0], {%1,%2,%3,%4};"
                 :: "r"(a), "r"(r0), "r"(r1), "r"(r2), "r"(r3) : "memory");
}

// ---------------- merged prepass (one launch) ---------------------------------
// blockIdx.x in [0, 24576): activation convert (which = idx/8192)
// blockIdx.x in [24576, 28672): weight transpose (which = (idx-24576)/1024)
#define ACT_BLOCKS (3 * (MTOT * DD / 4 / 256))   // 24576
#define WT_BLOCKS  (4 * (DD / 32) * (DD / 32))   // 4096

__global__ __launch_bounds__(256) void prepass_kernel(
    const float* __restrict__ q, const float* __restrict__ k,
    const float* __restrict__ v,
    const float* __restrict__ wq, const float* __restrict__ wk,
    const float* __restrict__ wv, const float* __restrict__ wo,
    __half* __restrict__ oaq, __half* __restrict__ oak, __half* __restrict__ oav,
    __half* __restrict__ owq, __half* __restrict__ owk,
    __half* __restrict__ owv, __half* __restrict__ owo)
{
    const int bx = blockIdx.x;
    const int tid = threadIdx.x;

    if (bx < ACT_BLOCKS) {
        const int which = bx / (ACT_BLOCKS / 3);
        const int blk   = bx % (ACT_BLOCKS / 3);
        const float* in = (which == 0) ? q : (which == 1) ? k : v;
        __half* out     = (which == 0) ? oaq : (which == 1) ? oak : oav;
        int i = blk * 256 + tid;
        float4 vv = ((const float4*)in)[i];
        uint2 o;
        o.x = pkh2(vv.x, vv.y);
        o.y = pkh2(vv.z, vv.w);
        ((uint2*)out)[i] = o;
    } else {
        const int w     = bx - ACT_BLOCKS;
        const int which = w >> 10;               // /1024
        const int rem   = w & 1023;
        const int n0    = (rem & 31) << 5;
        const int k0    = (rem >> 5) << 5;
        const float* in = (which == 0) ? wq : (which == 1) ? wk : (which == 2) ? wv : wo;
        __half* out     = (which == 0) ? owq : (which == 1) ? owk : (which == 2) ? owv : owo;
        const float sc  = (which == 0) ? 0.125f : 1.0f;

        __shared__ float tl[32][33];
        const int tx = tid & 31, ty = tid >> 5;  // 32 x 8
#pragma unroll
        for (int i = 0; i < 4; i++)
            tl[ty + i * 8][tx] = in[(size_t)(k0 + ty + i * 8) * DD + n0 + tx];
        __syncthreads();
#pragma unroll
        for (int i = 0; i < 4; i++)
            out[(size_t)(n0 + ty + i * 8) * DD + k0 + tx] =
                __float2half(tl[tx][ty + i * 8] * sc);
    }
}

// =============================================================================
// FP16 HMMA GEMM (fused QKV) — R10 configuration. blockIdx.z selects inputs.
// Block tile 128x128, K-tile 64, ldmatrix fragments, 3-stage cp.async ring.
// =============================================================================
#define HP 72
#define ROWB (HP*2)                       // 144 bytes per smem row
#define G_STG_H (2 * 128 * HP)
#define G_SMEM (3 * G_STG_H * 2)          // 110592 bytes
#define GNT (DD / 64)                     // 16 K-iterations

__global__ __launch_bounds__(256) void gemm_qkv_f16(
    const __half* __restrict__ A0, const __half* __restrict__ A1,
    const __half* __restrict__ A2,
    const __half* __restrict__ W0, const __half* __restrict__ W1,
    const __half* __restrict__ W2,
    const float* __restrict__ b0, const float* __restrict__ b1,
    const float* __restrict__ b2,
    __half* __restrict__ C0, __half* __restrict__ C1, __half* __restrict__ C2)
{
    extern __shared__ __half shh[];

    const int z = blockIdx.z;
    const __half* A  = (z == 0) ? A0 : (z == 1) ? A1 : A2;
    const __half* WT = (z == 0) ? W0 : (z == 1) ? W1 : W2;
    const float* bias = (z == 0) ? b0 : (z == 1) ? b1 : b2;
    __half* C        = (z == 0) ? C0 : (z == 1) ? C1 : C2;
    const float bsc  = (z == 0) ? 0.125f : 1.0f;

    const int tid  = threadIdx.x;
    const int wid  = tid >> 5;
    const int lane = tid & 31;
    const int g    = lane >> 2;
    const int t    = lane & 3;
    const int wm   = (wid & 3) << 5;
    const int wn   = (wid >> 2) << 6;
    const int m0   = blockIdx.y << 7;
    const int n0   = blockIdx.x << 7;

    const int lj = lane >> 3, lr = lane & 7;
    uint32_t aoff[2], boff[4];
#pragma unroll
    for (int mi = 0; mi < 2; mi++)
        aoff[mi] = (uint32_t)(((wm + (mi << 4) + ((lj & 1) << 3) + lr) * HP
                               + ((lj >> 1) << 3)) * 2);
#pragma unroll
    for (int np = 0; np < 4; np++)
        boff[np] = (uint32_t)(((wn + (np << 4) + ((lj & 1) << 3) + lr) * HP
                               + ((lj >> 1) << 3)) * 2);

    float c[2][8][4];
#pragma unroll
    for (int mi = 0; mi < 2; mi++)
#pragma unroll
        for (int ni = 0; ni < 8; ni++)
#pragma unroll
            for (int j = 0; j < 4; j++) c[mi][ni][j] = 0.f;

    const uint32_t shbase = smem_u32(shh);

    auto load_tile = [&](int kt, int stg) {
        const int k0 = kt << 6;
        const uint32_t sa = shbase + (stg * G_STG_H) * 2;
        const uint32_t sb = sa + 128 * ROWB;
#pragma unroll
        for (int j = 0; j < 4; j++) {
            int ca = j * 256 + tid;
            int row = ca >> 3, k8 = ca & 7;
            cpa16(sa + row * ROWB + (k8 << 4),
                  A + (size_t)(m0 + row) * DD + k0 + (k8 << 3));
        }
#pragma unroll
        for (int j = 0; j < 4; j++) {
            int cb = j * 256 + tid;
            int row = cb >> 3, k8 = cb & 7;
            cpa16(sb + row * ROWB + (k8 << 4),
                  WT + (size_t)(n0 + row) * DD + k0 + (k8 << 3));
        }
        cpa_commit();
    };

    load_tile(0, 0);
    load_tile(1, 1);

    for (int kt = 0; kt < GNT; kt++) {
        if (kt + 1 < GNT) cpa_wait<1>(); else cpa_wait<0>();
        __syncthreads();
        if (kt + 2 < GNT) load_tile(kt + 2, (kt + 2) % 3);

        const int stg = kt % 3;
        const uint32_t sa = shbase + (stg * G_STG_H) * 2;
        const uint32_t sb = sa + 128 * ROWB;

#pragma unroll
        for (int ks = 0; ks < 4; ks++) {
            uint32_t a[2][4], b[8][2];
#pragma unroll
            for (int mi = 0; mi < 2; mi++)
                ldsm4(a[mi][0], a[mi][1], a[mi][2], a[mi][3],
                      sa + aoff[mi] + ks * 32);
#pragma unroll
            for (int np = 0; np < 4; np++)
                ldsm4(b[2*np][0], b[2*np+1][0], b[2*np][1], b[2*np+1][1],
                      sb + boff[np] + ks * 32);
#pragma unroll
            for (int mi = 0; mi < 2; mi++)
#pragma unroll
                for (int ni = 0; ni < 8; ni++)
                    mma_f16(c[mi][ni], a[mi], b[ni]);
        }
    }

#pragma unroll
    for (int ni = 0; ni < 8; ni++) {
        int col = n0 + wn + (ni << 3) + (t << 1);
        float2 bv = *(const float2*)(bias + col);
        bv.x *= bsc; bv.y *= bsc;
#pragma unroll
        for (int mi = 0; mi < 2; mi++) {
            int row = m0 + wm + (mi << 4) + g;
            *(uint32_t*)(C + (size_t)row       * DD + col) =
                pkh2(c[mi][ni][0] + bv.x, c[mi][ni][1] + bv.y);
            *(uint32_t*)(C + (size_t)(row + 8) * DD + col) =
                pkh2(c[mi][ni][2] + bv.x, c[mi][ni][3] + bv.y);
        }
    }
}

// Single GEMM (output projection, fp32 out) — R10 configuration.
__global__ __launch_bounds__(256) void gemm_o_f16(
    const __half* __restrict__ A, const __half* __restrict__ WT,
    const float* __restrict__ bias, float* __restrict__ C)
{
    extern __shared__ __half shh[];

    const int tid  = threadIdx.x;
    const int wid  = tid >> 5;
    const int lane = tid & 31;
    const int g    = lane >> 2;
    const int t    = lane & 3;
    const int wm   = (wid & 3) << 5;
    const int wn   = (wid >> 2) << 6;
    const int m0   = blockIdx.y << 7;
    const int n0   = blockIdx.x << 7;

    const int lj = lane >> 3, lr = lane & 7;
    uint32_t aoff[2], boff[4];
#pragma unroll
    for (int mi = 0; mi < 2; mi++)
        aoff[mi] = (uint32_t)(((wm + (mi << 4) + ((lj & 1) << 3) + lr) * HP
                               + ((lj >> 1) << 3)) * 2);
#pragma unroll
    for (int np = 0; np < 4; np++)
        boff[np] = (uint32_t)(((wn + (np << 4) + ((lj & 1) << 3) + lr) * HP
                               + ((lj >> 1) << 3)) * 2);

    float c[2][8][4];
#pragma unroll
    for (int mi = 0; mi < 2; mi++)
#pragma unroll
        for (int ni = 0; ni < 8; ni++)
#pragma unroll
            for (int j = 0; j < 4; j++) c[mi][ni][j] = 0.f;

    const uint32_t shbase = smem_u32(shh);

    auto load_tile = [&](int kt, int stg) {
        const int k0 = kt << 6;
        const uint32_t sa = shbase + (stg * G_STG_H) * 2;
        const uint32_t sb = sa + 128 * ROWB;
#pragma unroll
        for (int j = 0; j < 4; j++) {
            int ca = j * 256 + tid;
            int row = ca >> 3, k8 = ca & 7;
            cpa16(sa + row * ROWB + (k8 << 4),
                  A + (size_t)(m0 + row) * DD + k0 + (k8 << 3));
        }
#pragma unroll
        for (int j = 0; j < 4; j++) {
            int cb = j * 256 + tid;
            int row = cb >> 3, k8 = cb & 7;
            cpa16(sb + row * ROWB + (k8 << 4),
                  WT + (size_t)(n0 + row) * DD + k0 + (k8 << 3));
        }
        cpa_commit();
    };

    load_tile(0, 0);
    load_tile(1, 1);

    for (int kt = 0; kt < GNT; kt++) {
        if (kt + 1 < GNT) cpa_wait<1>(); else cpa_wait<0>();
        __syncthreads();
        if (kt + 2 < GNT) load_tile(kt + 2, (kt + 2) % 3);

        const int stg = kt % 3;
        const uint32_t sa = shbase + (stg * G_STG_H) * 2;
        const uint32_t sb = sa + 128 * ROWB;

#pragma unroll
        for (int ks = 0; ks < 4; ks++) {
            uint32_t a[2][4], b[8][2];
#pragma unroll
            for (int mi = 0; mi < 2; mi++)
                ldsm4(a[mi][0], a[mi][1], a[mi][2], a[mi][3],
                      sa + aoff[mi] + ks * 32);
#pragma unroll
            for (int np = 0; np < 4; np++)
                ldsm4(b[2*np][0], b[2*np+1][0], b[2*np][1], b[2*np+1][1],
                      sb + boff[np] + ks * 32);
#pragma unroll
            for (int mi = 0; mi < 2; mi++)
#pragma unroll
                for (int ni = 0; ni < 8; ni++)
                    mma_f16(c[mi][ni], a[mi], b[ni]);
        }
    }

#pragma unroll
    for (int ni = 0; ni < 8; ni++) {
        int col = n0 + wn + (ni << 3) + (t << 1);
        float2 bv = *(const float2*)(bias + col);
#pragma unroll
        for (int mi = 0; mi < 2; mi++) {
            int row = m0 + wm + (mi << 4) + g;
            float2 v0 = make_float2(c[mi][ni][0] + bv.x, c[mi][ni][1] + bv.y);
            float2 v1 = make_float2(c[mi][ni][2] + bv.x, c[mi][ni][3] + bv.y);
            *(float2*)(C + (size_t)row       * DD + col) = v0;
            *(float2*)(C + (size_t)(row + 8) * DD + col) = v1;
        }
    }
}

// =============================================================================
// FP16 flash attention (causal) — R10 kernel with __launch_bounds__(128,3):
// reg cap 170 -> 3 CTAs/SM (smem 73.7 KB x 3 = 221 KB fits), 12 warps/SM.
// =============================================================================
#define ATT_SMEM ((128*HP + 2*64*HP + 2*64*HP + 128*HP) * 2)

__global__ __launch_bounds__(128, 3) void flash_f16_kernel(
    const __half* __restrict__ Q, const __half* __restrict__ K,
    const __half* __restrict__ V, __half* __restrict__ O)
{
    const int qt = (SS / 128 - 1) - blockIdx.x;
    const int h  = blockIdx.y;
    const int b  = blockIdx.z;
    const int tid  = threadIdx.x;
    const int warp = tid >> 5;
    const int lane = tid & 31;
    const int g    = lane >> 2;
    const int t    = lane & 3;
    const int wm   = warp << 5;

    extern __shared__ __half smh[];
    __half* Qs = smh;                    // [128][HP]
    __half* Ks = Qs + 128 * HP;          // [2][64][HP]
    __half* Vs = Ks + 2 * 64 * HP;       // [2][64][HP]
    __half* Ps = Vs + 2 * 64 * HP;       // [128][HP]

    const uint32_t qsb = smem_u32(Qs);
    const uint32_t ksbase = smem_u32(Ks);
    const uint32_t vsbase = smem_u32(Vs);
    const uint32_t psb = smem_u32(Ps);

    const int lj = lane >> 3, lr = lane & 7;
    uint32_t moff[2], koff[4];
#pragma unroll
    for (int mi = 0; mi < 2; mi++)
        moff[mi] = (uint32_t)(((wm + (mi << 4) + ((lj & 1) << 3) + lr) * HP
                               + ((lj >> 1) << 3)) * 2);
#pragma unroll
    for (int np = 0; np < 4; np++)
        koff[np] = (uint32_t)((((np << 4) + ((lj & 1) << 3) + lr) * HP
                               + ((lj >> 1) << 3)) * 2);

    const int vrow = ((lane >> 3) & 1) * 8 + (lane & 7);
    const int vcol = (lane >> 4) * 8;

    const __half* Kh0 = K + ((size_t)(b * SS)) * DD + h * DKH;
    const __half* Vh0 = V + ((size_t)(b * SS)) * DD + h * DKH;

    auto load_kv = [&](int kt, int buf) {
        const __half* Kb = Kh0 + (size_t)(kt * 64) * DD;
        const __half* Vb = Vh0 + (size_t)(kt * 64) * DD;
        const uint32_t kb = ksbase + buf * 64 * ROWB;
        const uint32_t vb = vsbase + buf * 64 * ROWB;
#pragma unroll
        for (int i = 0; i < 4; i++) {
            int e = i * 128 + tid;
            int r = e >> 3;
            int c8 = e & 7;
            cpa16(kb + r * ROWB + (c8 << 4), Kb + (size_t)r * DD + (c8 << 3));
            cpa16(vb + r * ROWB + (c8 << 4), Vb + (size_t)r * DD + (c8 << 3));
        }
        cpa_commit();
    };

    // ---- load Q tile ----
    const __half* Qb = Q + ((size_t)(b * SS + qt * 128)) * DD + h * DKH;
#pragma unroll
    for (int i = 0; i < 8; i++) {
        int e = i * 128 + tid;
        int r = e >> 3;
        int c8 = e & 7;
        *(uint4*)&Qs[r * HP + (c8 << 3)] = *(const uint4*)(Qb + (size_t)r * DD + (c8 << 3));
    }

    load_kv(0, 0);

    float m_i[2][2], l_i[2][2], co[2][8][4];
#pragma unroll
    for (int mi = 0; mi < 2; mi++)
#pragma unroll
        for (int hh = 0; hh < 2; hh++) { m_i[mi][hh] = -INFINITY; l_i[mi][hh] = 0.f; }
#pragma unroll
    for (int mi = 0; mi < 2; mi++)
#pragma unroll
        for (int ni = 0; ni < 8; ni++)
#pragma unroll
            for (int j = 0; j < 4; j++) co[mi][ni][j] = 0.f;

    const uint32_t bones = 0x3C003C00u;  // half2(1,1)
    const int ktmax = 2 * qt + 1;

    for (int kt = 0; kt <= ktmax; kt++) {
        __syncthreads();
        if (kt < ktmax) {
            load_kv(kt + 1, (kt + 1) & 1);
            cpa_wait<1>();
        } else {
            cpa_wait<0>();
        }
        __syncthreads();

        const uint32_t ktile = ksbase + (kt & 1) * 64 * ROWB;
        const uint32_t vtile = vsbase + (kt & 1) * 64 * ROWB;

        // ---- S = Q K^T (pre-scaled via wq) ----
        float cs[2][8][4];
#pragma unroll
        for (int mi = 0; mi < 2; mi++)
#pragma unroll
            for (int ni = 0; ni < 8; ni++)
#pragma unroll
                for (int j = 0; j < 4; j++) cs[mi][ni][j] = 0.f;

#pragma unroll
        for (int ks = 0; ks < 4; ks++) {
            uint32_t a[2][4], bf[8][2];
#pragma unroll
            for (int mi = 0; mi < 2; mi++)
                ldsm4(a[mi][0], a[mi][1], a[mi][2], a[mi][3],
                      qsb + moff[mi] + ks * 32);
#pragma unroll
            for (int np = 0; np < 4; np++)
                ldsm4(bf[2*np][0], bf[2*np+1][0], bf[2*np][1], bf[2*np+1][1],
                      ktile + koff[np] + ks * 32);
#pragma unroll
            for (int mi = 0; mi < 2; mi++)
#pragma unroll
                for (int ni = 0; ni < 8; ni++)
                    mma_f16(cs[mi][ni], a[mi], bf[ni]);
        }

        // ---- causal mask (only last two tiles) ----
        if (kt >= 2 * qt) {
#pragma unroll
            for (int mi = 0; mi < 2; mi++)
#pragma unroll
                for (int ni = 0; ni < 8; ni++)
#pragma unroll
                    for (int j = 0; j < 4; j++) {
                        int row = qt * 128 + wm + (mi << 4) + g + ((j >> 1) << 3);
                        int col = kt * 64 + (ni << 3) + (t << 1) + (j & 1);
                        if (col > row) cs[mi][ni][j] = -1e9f;
                    }
        }

        // ---- online softmax: max + alpha ----
        float ml[2][2], al[2][2];
#pragma unroll
        for (int mi = 0; mi < 2; mi++)
#pragma unroll
            for (int hh = 0; hh < 2; hh++) {
                float mx = -INFINITY;
#pragma unroll
                for (int ni = 0; ni < 8; ni++)
                    mx = fmaxf(mx, fmaxf(cs[mi][ni][2*hh], cs[mi][ni][2*hh+1]));
                mx = fmaxf(mx, __shfl_xor_sync(0xffffffffu, mx, 1));
                mx = fmaxf(mx, __shfl_xor_sync(0xffffffffu, mx, 2));
                float m2 = fmaxf(m_i[mi][hh], mx);
                al[mi][hh] = __expf(m_i[mi][hh] - m2);
                m_i[mi][hh] = m2;
                ml[mi][hh] = m2 * L2E;
            }
#pragma unroll
        for (int mi = 0; mi < 2; mi++)
#pragma unroll
            for (int ni = 0; ni < 8; ni++)
#pragma unroll
                for (int j = 0; j < 4; j++)
                    co[mi][ni][j] *= al[mi][j >> 1];

        // ---- P = exp2(S*log2e - m*log2e) in half; stmatrix ----
#pragma unroll
        for (int mi = 0; mi < 2; mi++) {
#pragma unroll
            for (int np = 0; np < 4; np++) {
                int ni = 2 * np, ni1 = 2 * np + 1;
                uint32_t r0 = ex2h2(pkh2(fmaf(cs[mi][ni ][0], L2E, -ml[mi][0]),
                                         fmaf(cs[mi][ni ][1], L2E, -ml[mi][0])));
                uint32_t r1 = ex2h2(pkh2(fmaf(cs[mi][ni ][2], L2E, -ml[mi][1]),
                                         fmaf(cs[mi][ni ][3], L2E, -ml[mi][1])));
                uint32_t r2 = ex2h2(pkh2(fmaf(cs[mi][ni1][0], L2E, -ml[mi][0]),
                                         fmaf(cs[mi][ni1][1], L2E, -ml[mi][0])));
                uint32_t r3 = ex2h2(pkh2(fmaf(cs[mi][ni1][2], L2E, -ml[mi][1]),
                                         fmaf(cs[mi][ni1][3], L2E, -ml[mi][1])));
                stsm4(psb + moff[mi] + np * 32, r0, r1, r2, r3);
            }
        }
        __syncwarp();

        // ---- O += P @ V  and  l-rowsum via MMA with ones ----
        float csum[2][4];
#pragma unroll
        for (int mi = 0; mi < 2; mi++)
#pragma unroll
            for (int j = 0; j < 4; j++) csum[mi][j] = 0.f;

#pragma unroll
        for (int ks = 0; ks < 4; ks++) {
            uint32_t a[2][4], bf[8][2];
#pragma unroll
            for (int mi = 0; mi < 2; mi++)
                ldsm4(a[mi][0], a[mi][1], a[mi][2], a[mi][3],
                      psb + moff[mi] + ks * 32);
#pragma unroll
            for (int nn = 0; nn < 4; nn++) {
                uint32_t addr = vtile + ((ks << 4) + vrow) * ROWB + ((nn << 4) + vcol) * 2;
                ldsm4t(bf[2*nn][0], bf[2*nn][1], bf[2*nn+1][0], bf[2*nn+1][1], addr);
            }
#pragma unroll
            for (int mi = 0; mi < 2; mi++) {
                uint32_t bo[2] = {bones, bones};
                mma_f16(csum[mi], a[mi], bo);
#pragma unroll
                for (int ni = 0; ni < 8; ni++)
                    mma_f16(co[mi][ni], a[mi], bf[ni]);
            }
        }

#pragma unroll
        for (int mi = 0; mi < 2; mi++)
#pragma unroll
            for (int hh = 0; hh < 2; hh++)
                l_i[mi][hh] = l_i[mi][hh] * al[mi][hh] + csum[mi][2*hh];
    }

    // ---- epilogue ----
#pragma unroll
    for (int mi = 0; mi < 2; mi++)
#pragma unroll
        for (int hh = 0; hh < 2; hh++) {
            float inv = 1.f / l_i[mi][hh];
            int row = qt * 128 + wm + (mi << 4) + g + (hh << 3);
            __half* ob = O + ((size_t)(b * SS + row)) * DD + h * DKH;
#pragma unroll
            for (int ni = 0; ni < 8; ni++) {
                int col = (ni << 3) + (t << 1);
                *(uint32_t*)(ob + col) = pkh2(co[mi][ni][2*hh] * inv,
                                              co[mi][ni][2*hh+1] * inv);
            }
        }
}

// =============================================================================
// Launch
// =============================================================================
extern "C" void kernel_launch(void* const* d_in, const int* in_sizes, int n_in,
                              void* d_out, int out_size)
{
    const float* q  = (const float*)d_in[1];
    const float* k  = (const float*)d_in[2];
    const float* v  = (const float*)d_in[3];
    const float* wq = (const float*)d_in[5];
    const float* bq = (const float*)d_in[6];
    const float* wk = (const float*)d_in[7];
    const float* bk = (const float*)d_in[8];
    const float* wv = (const float*)d_in[9];
    const float* bv = (const float*)d_in[10];
    const float* wo = (const float*)d_in[11];
    const float* bo = (const float*)d_in[12];
    float* out = (float*)d_out;

    __half *aq, *ak, *av, *qh, *kh, *vh, *aoh, *wtq, *wtk, *wtv, *wto;
    cudaGetSymbolAddress((void**)&aq,  g_Aq);
    cudaGetSymbolAddress((void**)&ak,  g_Ak);
    cudaGetSymbolAddress((void**)&av,  g_Av);
    cudaGetSymbolAddress((void**)&qh,  g_Qh);
    cudaGetSymbolAddress((void**)&kh,  g_Kh);
    cudaGetSymbolAddress((void**)&vh,  g_Vh);
    cudaGetSymbolAddress((void**)&aoh, g_AOh);
    cudaGetSymbolAddress((void**)&wtq, g_Wq);
    cudaGetSymbolAddress((void**)&wtk, g_Wk);
    cudaGetSymbolAddress((void**)&wtv, g_Wv);
    cudaGetSymbolAddress((void**)&wto, g_Wo);

    cudaFuncSetAttribute(flash_f16_kernel,
                         cudaFuncAttributeMaxDynamicSharedMemorySize, ATT_SMEM);
    cudaFuncSetAttribute(gemm_qkv_f16,
                         cudaFuncAttributeMaxDynamicSharedMemorySize, G_SMEM);
    cudaFuncSetAttribute(gemm_o_f16,
                         cudaFuncAttributeMaxDynamicSharedMemorySize, G_SMEM);

    // ---- merged prepass (1 launch) ----
    prepass_kernel<<<ACT_BLOCKS + WT_BLOCKS, 256>>>(
        q, k, v, wq, wk, wv, wo,
        aq, ak, av, wtq, wtk, wtv, wto);

    // ---- fused QKV projections (R10 config) ----
    dim3 gblk(256);
    dim3 gqkv(DD / 128, MTOT / 128, 3);   // (8, 64, 3)
    gemm_qkv_f16<<<gqkv, gblk, G_SMEM>>>(aq, ak, av, wtq, wtk, wtv,
                                         bq, bk, bv, qh, kh, vh);

    // ---- attention (R10 config + occupancy 3) ----
    dim3 agrid(SS / 128, HH, BB);         // (16, 16, 4)
    flash_f16_kernel<<<agrid, dim3(128), ATT_SMEM>>>(qh, kh, vh, aoh);

    // ---- output projection (R10 config, fp32 out) ----
    dim3 go(DD / 128, MTOT / 128);
    gemm_o_f16<<<go, gblk, G_SMEM>>>(aoh, wto, bo, out);
}

// round 15
// speedup vs baseline: 1.0377x; 1.0194x over previous
#include <cuda_runtime.h>
#include <cuda_fp16.h>
#include <math.h>
#include <stdint.h>

// Problem constants
#define BB 4
#define SS 2048
#define DD 1024
#define HH 16
#define DKH 64
#define MTOT (BB*SS)          // 8192 rows

#define L2E 1.4426950408889634f

// ---------------- scratch (static device globals; no allocation) -------------
__device__ __half g_Aq[MTOT*DD];
__device__ __half g_Ak[MTOT*DD];
__device__ __half g_Av[MTOT*DD];
__device__ __half g_Qh[MTOT*DD];
__device__ __half g_Kh[MTOT*DD];
__device__ __half g_Vh[MTOT*DD];
__device__ __half g_AOh[MTOT*DD];
__device__ __half g_Wq[DD*DD];     // WT[n][k] half (wq pre-scaled by 0.125)
__device__ __half g_Wk[DD*DD];
__device__ __half g_Wv[DD*DD];
__device__ __half g_Wo[DD*DD];

// ---------------- helpers -----------------------------------------------------
__device__ __forceinline__ uint32_t pkh2(float a, float b) {
    __half2 h = __floats2half2_rn(a, b);
    return *(uint32_t*)&h;
}
__device__ __forceinline__ uint32_t ex2h2(uint32_t x) {
    uint32_t r;
    asm("ex2.approx.f16x2 %0, %1;" : "=r"(r) : "r"(x));
    return r;
}
__device__ __forceinline__ void cpa16(uint32_t smem, const void* gmem) {
    asm volatile("cp.async.cg.shared.global [%0], [%1], 16;" :: "r"(smem), "l"(gmem));
}
__device__ __forceinline__ void cpa_commit() {
    asm volatile("cp.async.commit_group;");
}
template<int N> __device__ __forceinline__ void cpa_wait() {
    asm volatile("cp.async.wait_group %0;" :: "n"(N));
}
__device__ __forceinline__ uint32_t smem_u32(const void* p) {
    uint32_t a;
    asm("{ .reg .u64 t; cvta.to.shared.u64 t, %1; cvt.u32.u64 %0, t; }"
        : "=r"(a) : "l"(p));
    return a;
}
__device__ __forceinline__ void mma_f16(
    float c[4], const uint32_t a[4], const uint32_t b[2])
{
    asm volatile(
        "mma.sync.aligned.m16n8k16.row.col.f32.f16.f16.f32 "
        "{%0,%1,%2,%3}, {%4,%5,%6,%7}, {%8,%9}, {%0,%1,%2,%3};"
        : "+f"(c[0]), "+f"(c[1]), "+f"(c[2]), "+f"(c[3])
        : "r"(a[0]), "r"(a[1]), "r"(a[2]), "r"(a[3]),
          "r"(b[0]), "r"(b[1]));
}
__device__ __forceinline__ void ldsm4(
    uint32_t& r0, uint32_t& r1, uint32_t& r2, uint32_t& r3, uint32_t a)
{
    asm volatile("ldmatrix.sync.aligned.m8n8.x4.shared.b16 {%0,%1,%2,%3}, [%4];"
                 : "=r"(r0), "=r"(r1), "=r"(r2), "=r"(r3) : "r"(a));
}
__device__ __forceinline__ void ldsm4t(
    uint32_t& r0, uint32_t& r1, uint32_t& r2, uint32_t& r3, uint32_t a)
{
    asm volatile("ldmatrix.sync.aligned.m8n8.x4.trans.shared.b16 {%0,%1,%2,%3}, [%4];"
                 : "=r"(r0), "=r"(r1), "=r"(r2), "=r"(r3) : "r"(a));
}
__device__ __forceinline__ void stsm4(
    uint32_t a, uint32_t r0, uint32_t r1, uint32_t r2, uint32_t r3)
{
    asm volatile("stmatrix.sync.aligned.m8n8.x4.shared.b16 [%0], {%1,%2,%3,%4};"
                 :: "r"(a), "r"(r0), "r"(r1), "r"(r2), "r"(r3) : "memory");
}

// ---------------- merged prepass (one launch) ---------------------------------
#define ACT_BLOCKS (3 * (MTOT * DD / 4 / 256))   // 24576
#define WT_BLOCKS  (4 * (DD / 32) * (DD / 32))   // 4096

__global__ __launch_bounds__(256) void prepass_kernel(
    const float* __restrict__ q, const float* __restrict__ k,
    const float* __restrict__ v,
    const float* __restrict__ wq, const float* __restrict__ wk,
    const float* __restrict__ wv, const float* __restrict__ wo,
    __half* __restrict__ oaq, __half* __restrict__ oak, __half* __restrict__ oav,
    __half* __restrict__ owq, __half* __restrict__ owk,
    __half* __restrict__ owv, __half* __restrict__ owo)
{
    const int bx = blockIdx.x;
    const int tid = threadIdx.x;

    if (bx < ACT_BLOCKS) {
        const int which = bx / (ACT_BLOCKS / 3);
        const int blk   = bx % (ACT_BLOCKS / 3);
        const float* in = (which == 0) ? q : (which == 1) ? k : v;
        __half* out     = (which == 0) ? oaq : (which == 1) ? oak : oav;
        int i = blk * 256 + tid;
        float4 vv = ((const float4*)in)[i];
        uint2 o;
        o.x = pkh2(vv.x, vv.y);
        o.y = pkh2(vv.z, vv.w);
        ((uint2*)out)[i] = o;
    } else {
        const int w     = bx - ACT_BLOCKS;
        const int which = w >> 10;
        const int rem   = w & 1023;
        const int n0    = (rem & 31) << 5;
        const int k0    = (rem >> 5) << 5;
        const float* in = (which == 0) ? wq : (which == 1) ? wk : (which == 2) ? wv : wo;
        __half* out     = (which == 0) ? owq : (which == 1) ? owk : (which == 2) ? owv : owo;
        const float sc  = (which == 0) ? 0.125f : 1.0f;

        __shared__ float tl[32][33];
        const int tx = tid & 31, ty = tid >> 5;
#pragma unroll
        for (int i = 0; i < 4; i++)
            tl[ty + i * 8][tx] = in[(size_t)(k0 + ty + i * 8) * DD + n0 + tx];
        __syncthreads();
#pragma unroll
        for (int i = 0; i < 4; i++)
            out[(size_t)(n0 + ty + i * 8) * DD + k0 + tx] =
                __float2half(tl[tx][ty + i * 8] * sc);
    }
}

// =============================================================================
// FP16 HMMA GEMM (fused QKV) — R10 configuration. blockIdx.z selects inputs.
// Block tile 128x128, K-tile 64, ldmatrix fragments, 3-stage cp.async ring.
// =============================================================================
#define HP 72
#define ROWB (HP*2)                       // 144 bytes per smem row
#define G_STG_H (2 * 128 * HP)
#define G_SMEM (3 * G_STG_H * 2)          // 110592 bytes
#define GNT (DD / 64)                     // 16 K-iterations

__global__ __launch_bounds__(256) void gemm_qkv_f16(
    const __half* __restrict__ A0, const __half* __restrict__ A1,
    const __half* __restrict__ A2,
    const __half* __restrict__ W0, const __half* __restrict__ W1,
    const __half* __restrict__ W2,
    const float* __restrict__ b0, const float* __restrict__ b1,
    const float* __restrict__ b2,
    __half* __restrict__ C0, __half* __restrict__ C1, __half* __restrict__ C2)
{
    extern __shared__ __half shh[];

    const int z = blockIdx.z;
    const __half* A  = (z == 0) ? A0 : (z == 1) ? A1 : A2;
    const __half* WT = (z == 0) ? W0 : (z == 1) ? W1 : W2;
    const float* bias = (z == 0) ? b0 : (z == 1) ? b1 : b2;
    __half* C        = (z == 0) ? C0 : (z == 1) ? C1 : C2;
    const float bsc  = (z == 0) ? 0.125f : 1.0f;

    const int tid  = threadIdx.x;
    const int wid  = tid >> 5;
    const int lane = tid & 31;
    const int g    = lane >> 2;
    const int t    = lane & 3;
    const int wm   = (wid & 3) << 5;
    const int wn   = (wid >> 2) << 6;
    const int m0   = blockIdx.y << 7;
    const int n0   = blockIdx.x << 7;

    const int lj = lane >> 3, lr = lane & 7;
    uint32_t aoff[2], boff[4];
#pragma unroll
    for (int mi = 0; mi < 2; mi++)
        aoff[mi] = (uint32_t)(((wm + (mi << 4) + ((lj & 1) << 3) + lr) * HP
                               + ((lj >> 1) << 3)) * 2);
#pragma unroll
    for (int np = 0; np < 4; np++)
        boff[np] = (uint32_t)(((wn + (np << 4) + ((lj & 1) << 3) + lr) * HP
                               + ((lj >> 1) << 3)) * 2);

    float c[2][8][4];
#pragma unroll
    for (int mi = 0; mi < 2; mi++)
#pragma unroll
        for (int ni = 0; ni < 8; ni++)
#pragma unroll
            for (int j = 0; j < 4; j++) c[mi][ni][j] = 0.f;

    const uint32_t shbase = smem_u32(shh);

    auto load_tile = [&](int kt, int stg) {
        const int k0 = kt << 6;
        const uint32_t sa = shbase + (stg * G_STG_H) * 2;
        const uint32_t sb = sa + 128 * ROWB;
#pragma unroll
        for (int j = 0; j < 4; j++) {
            int ca = j * 256 + tid;
            int row = ca >> 3, k8 = ca & 7;
            cpa16(sa + row * ROWB + (k8 << 4),
                  A + (size_t)(m0 + row) * DD + k0 + (k8 << 3));
        }
#pragma unroll
        for (int j = 0; j < 4; j++) {
            int cb = j * 256 + tid;
            int row = cb >> 3, k8 = cb & 7;
            cpa16(sb + row * ROWB + (k8 << 4),
                  WT + (size_t)(n0 + row) * DD + k0 + (k8 << 3));
        }
        cpa_commit();
    };

    load_tile(0, 0);
    load_tile(1, 1);

    for (int kt = 0; kt < GNT; kt++) {
        if (kt + 1 < GNT) cpa_wait<1>(); else cpa_wait<0>();
        __syncthreads();
        if (kt + 2 < GNT) load_tile(kt + 2, (kt + 2) % 3);

        const int stg = kt % 3;
        const uint32_t sa = shbase + (stg * G_STG_H) * 2;
        const uint32_t sb = sa + 128 * ROWB;

#pragma unroll
        for (int ks = 0; ks < 4; ks++) {
            uint32_t a[2][4], b[8][2];
#pragma unroll
            for (int mi = 0; mi < 2; mi++)
                ldsm4(a[mi][0], a[mi][1], a[mi][2], a[mi][3],
                      sa + aoff[mi] + ks * 32);
#pragma unroll
            for (int np = 0; np < 4; np++)
                ldsm4(b[2*np][0], b[2*np+1][0], b[2*np][1], b[2*np+1][1],
                      sb + boff[np] + ks * 32);
#pragma unroll
            for (int mi = 0; mi < 2; mi++)
#pragma unroll
                for (int ni = 0; ni < 8; ni++)
                    mma_f16(c[mi][ni], a[mi], b[ni]);
        }
    }

#pragma unroll
    for (int ni = 0; ni < 8; ni++) {
        int col = n0 + wn + (ni << 3) + (t << 1);
        float2 bv = *(const float2*)(bias + col);
        bv.x *= bsc; bv.y *= bsc;
#pragma unroll
        for (int mi = 0; mi < 2; mi++) {
            int row = m0 + wm + (mi << 4) + g;
            *(uint32_t*)(C + (size_t)row       * DD + col) =
                pkh2(c[mi][ni][0] + bv.x, c[mi][ni][1] + bv.y);
            *(uint32_t*)(C + (size_t)(row + 8) * DD + col) =
                pkh2(c[mi][ni][2] + bv.x, c[mi][ni][3] + bv.y);
        }
    }
}

// Single GEMM (output projection, fp32 out) — R10 configuration.
__global__ __launch_bounds__(256) void gemm_o_f16(
    const __half* __restrict__ A, const __half* __restrict__ WT,
    const float* __restrict__ bias, float* __restrict__ C)
{
    extern __shared__ __half shh[];

    const int tid  = threadIdx.x;
    const int wid  = tid >> 5;
    const int lane = tid & 31;
    const int g    = lane >> 2;
    const int t    = lane & 3;
    const int wm   = (wid & 3) << 5;
    const int wn   = (wid >> 2) << 6;
    const int m0   = blockIdx.y << 7;
    const int n0   = blockIdx.x << 7;

    const int lj = lane >> 3, lr = lane & 7;
    uint32_t aoff[2], boff[4];
#pragma unroll
    for (int mi = 0; mi < 2; mi++)
        aoff[mi] = (uint32_t)(((wm + (mi << 4) + ((lj & 1) << 3) + lr) * HP
                               + ((lj >> 1) << 3)) * 2);
#pragma unroll
    for (int np = 0; np < 4; np++)
        boff[np] = (uint32_t)(((wn + (np << 4) + ((lj & 1) << 3) + lr) * HP
                               + ((lj >> 1) << 3)) * 2);

    float c[2][8][4];
#pragma unroll
    for (int mi = 0; mi < 2; mi++)
#pragma unroll
        for (int ni = 0; ni < 8; ni++)
#pragma unroll
            for (int j = 0; j < 4; j++) c[mi][ni][j] = 0.f;

    const uint32_t shbase = smem_u32(shh);

    auto load_tile = [&](int kt, int stg) {
        const int k0 = kt << 6;
        const uint32_t sa = shbase + (stg * G_STG_H) * 2;
        const uint32_t sb = sa + 128 * ROWB;
#pragma unroll
        for (int j = 0; j < 4; j++) {
            int ca = j * 256 + tid;
            int row = ca >> 3, k8 = ca & 7;
            cpa16(sa + row * ROWB + (k8 << 4),
                  A + (size_t)(m0 + row) * DD + k0 + (k8 << 3));
        }
#pragma unroll
        for (int j = 0; j < 4; j++) {
            int cb = j * 256 + tid;
            int row = cb >> 3, k8 = cb & 7;
            cpa16(sb + row * ROWB + (k8 << 4),
                  WT + (size_t)(n0 + row) * DD + k0 + (k8 << 3));
        }
        cpa_commit();
    };

    load_tile(0, 0);
    load_tile(1, 1);

    for (int kt = 0; kt < GNT; kt++) {
        if (kt + 1 < GNT) cpa_wait<1>(); else cpa_wait<0>();
        __syncthreads();
        if (kt + 2 < GNT) load_tile(kt + 2, (kt + 2) % 3);

        const int stg = kt % 3;
        const uint32_t sa = shbase + (stg * G_STG_H) * 2;
        const uint32_t sb = sa + 128 * ROWB;

#pragma unroll
        for (int ks = 0; ks < 4; ks++) {
            uint32_t a[2][4], b[8][2];
#pragma unroll
            for (int mi = 0; mi < 2; mi++)
                ldsm4(a[mi][0], a[mi][1], a[mi][2], a[mi][3],
                      sa + aoff[mi] + ks * 32);
#pragma unroll
            for (int np = 0; np < 4; np++)
                ldsm4(b[2*np][0], b[2*np+1][0], b[2*np][1], b[2*np+1][1],
                      sb + boff[np] + ks * 32);
#pragma unroll
            for (int mi = 0; mi < 2; mi++)
#pragma unroll
                for (int ni = 0; ni < 8; ni++)
                    mma_f16(c[mi][ni], a[mi], b[ni]);
        }
    }

#pragma unroll
    for (int ni = 0; ni < 8; ni++) {
        int col = n0 + wn + (ni << 3) + (t << 1);
        float2 bv = *(const float2*)(bias + col);
#pragma unroll
        for (int mi = 0; mi < 2; mi++) {
            int row = m0 + wm + (mi << 4) + g;
            float2 v0 = make_float2(c[mi][ni][0] + bv.x, c[mi][ni][1] + bv.y);
            float2 v1 = make_float2(c[mi][ni][2] + bv.x, c[mi][ni][3] + bv.y);
            *(float2*)(C + (size_t)row       * DD + col) = v0;
            *(float2*)(C + (size_t)(row + 8) * DD + col) = v1;
        }
    }
}

// =============================================================================
// FP16 flash attention (causal) — exact R10 kernel (no min-blocks clause):
// 128 threads / 4 warps, warp tile 32x64, ldmatrix/stmatrix fragments,
// ex2.f16x2 softmax, ones-MMA rowsum, cp.async double-buffered K/V.
// =============================================================================
#define ATT_SMEM ((128*HP + 2*64*HP + 2*64*HP + 128*HP) * 2)

__global__ __launch_bounds__(128) void flash_f16_kernel(
    const __half* __restrict__ Q, const __half* __restrict__ K,
    const __half* __restrict__ V, __half* __restrict__ O)
{
    const int qt = (SS / 128 - 1) - blockIdx.x;
    const int h  = blockIdx.y;
    const int b  = blockIdx.z;
    const int tid  = threadIdx.x;
    const int warp = tid >> 5;
    const int lane = tid & 31;
    const int g    = lane >> 2;
    const int t    = lane & 3;
    const int wm   = warp << 5;

    extern __shared__ __half smh[];
    __half* Qs = smh;                    // [128][HP]
    __half* Ks = Qs + 128 * HP;          // [2][64][HP]
    __half* Vs = Ks + 2 * 64 * HP;       // [2][64][HP]
    __half* Ps = Vs + 2 * 64 * HP;       // [128][HP]

    const uint32_t qsb = smem_u32(Qs);
    const uint32_t ksbase = smem_u32(Ks);
    const uint32_t vsbase = smem_u32(Vs);
    const uint32_t psb = smem_u32(Ps);

    const int lj = lane >> 3, lr = lane & 7;
    uint32_t moff[2], koff[4];
#pragma unroll
    for (int mi = 0; mi < 2; mi++)
        moff[mi] = (uint32_t)(((wm + (mi << 4) + ((lj & 1) << 3) + lr) * HP
                               + ((lj >> 1) << 3)) * 2);
#pragma unroll
    for (int np = 0; np < 4; np++)
        koff[np] = (uint32_t)((((np << 4) + ((lj & 1) << 3) + lr) * HP
                               + ((lj >> 1) << 3)) * 2);

    const int vrow = ((lane >> 3) & 1) * 8 + (lane & 7);
    const int vcol = (lane >> 4) * 8;

    const __half* Kh0 = K + ((size_t)(b * SS)) * DD + h * DKH;
    const __half* Vh0 = V + ((size_t)(b * SS)) * DD + h * DKH;

    auto load_kv = [&](int kt, int buf) {
        const __half* Kb = Kh0 + (size_t)(kt * 64) * DD;
        const __half* Vb = Vh0 + (size_t)(kt * 64) * DD;
        const uint32_t kb = ksbase + buf * 64 * ROWB;
        const uint32_t vb = vsbase + buf * 64 * ROWB;
#pragma unroll
        for (int i = 0; i < 4; i++) {
            int e = i * 128 + tid;
            int r = e >> 3;
            int c8 = e & 7;
            cpa16(kb + r * ROWB + (c8 << 4), Kb + (size_t)r * DD + (c8 << 3));
            cpa16(vb + r * ROWB + (c8 << 4), Vb + (size_t)r * DD + (c8 << 3));
        }
        cpa_commit();
    };

    // ---- load Q tile ----
    const __half* Qb = Q + ((size_t)(b * SS + qt * 128)) * DD + h * DKH;
#pragma unroll
    for (int i = 0; i < 8; i++) {
        int e = i * 128 + tid;
        int r = e >> 3;
        int c8 = e & 7;
        *(uint4*)&Qs[r * HP + (c8 << 3)] = *(const uint4*)(Qb + (size_t)r * DD + (c8 << 3));
    }

    load_kv(0, 0);

    float m_i[2][2], l_i[2][2], co[2][8][4];
#pragma unroll
    for (int mi = 0; mi < 2; mi++)
#pragma unroll
        for (int hh = 0; hh < 2; hh++) { m_i[mi][hh] = -INFINITY; l_i[mi][hh] = 0.f; }
#pragma unroll
    for (int mi = 0; mi < 2; mi++)
#pragma unroll
        for (int ni = 0; ni < 8; ni++)
#pragma unroll
            for (int j = 0; j < 4; j++) co[mi][ni][j] = 0.f;

    const uint32_t bones = 0x3C003C00u;  // half2(1,1)
    const int ktmax = 2 * qt + 1;

    for (int kt = 0; kt <= ktmax; kt++) {
        __syncthreads();
        if (kt < ktmax) {
            load_kv(kt + 1, (kt + 1) & 1);
            cpa_wait<1>();
        } else {
            cpa_wait<0>();
        }
        __syncthreads();

        const uint32_t ktile = ksbase + (kt & 1) * 64 * ROWB;
        const uint32_t vtile = vsbase + (kt & 1) * 64 * ROWB;

        // ---- S = Q K^T (pre-scaled via wq) ----
        float cs[2][8][4];
#pragma unroll
        for (int mi = 0; mi < 2; mi++)
#pragma unroll
            for (int ni = 0; ni < 8; ni++)
#pragma unroll
                for (int j = 0; j < 4; j++) cs[mi][ni][j] = 0.f;

#pragma unroll
        for (int ks = 0; ks < 4; ks++) {
            uint32_t a[2][4], bf[8][2];
#pragma unroll
            for (int mi = 0; mi < 2; mi++)
                ldsm4(a[mi][0], a[mi][1], a[mi][2], a[mi][3],
                      qsb + moff[mi] + ks * 32);
#pragma unroll
            for (int np = 0; np < 4; np++)
                ldsm4(bf[2*np][0], bf[2*np+1][0], bf[2*np][1], bf[2*np+1][1],
                      ktile + koff[np] + ks * 32);
#pragma unroll
            for (int mi = 0; mi < 2; mi++)
#pragma unroll
                for (int ni = 0; ni < 8; ni++)
                    mma_f16(cs[mi][ni], a[mi], bf[ni]);
        }

        // ---- causal mask (only last two tiles) ----
        if (kt >= 2 * qt) {
#pragma unroll
            for (int mi = 0; mi < 2; mi++)
#pragma unroll
                for (int ni = 0; ni < 8; ni++)
#pragma unroll
                    for (int j = 0; j < 4; j++) {
                        int row = qt * 128 + wm + (mi << 4) + g + ((j >> 1) << 3);
                        int col = kt * 64 + (ni << 3) + (t << 1) + (j & 1);
                        if (col > row) cs[mi][ni][j] = -1e9f;
                    }
        }

        // ---- online softmax: max + alpha ----
        float ml[2][2], al[2][2];
#pragma unroll
        for (int mi = 0; mi < 2; mi++)
#pragma unroll
            for (int hh = 0; hh < 2; hh++) {
                float mx = -INFINITY;
#pragma unroll
                for (int ni = 0; ni < 8; ni++)
                    mx = fmaxf(mx, fmaxf(cs[mi][ni][2*hh], cs[mi][ni][2*hh+1]));
                mx = fmaxf(mx, __shfl_xor_sync(0xffffffffu, mx, 1));
                mx = fmaxf(mx, __shfl_xor_sync(0xffffffffu, mx, 2));
                float m2 = fmaxf(m_i[mi][hh], mx);
                al[mi][hh] = __expf(m_i[mi][hh] - m2);
                m_i[mi][hh] = m2;
                ml[mi][hh] = m2 * L2E;
            }
#pragma unroll
        for (int mi = 0; mi < 2; mi++)
#pragma unroll
            for (int ni = 0; ni < 8; ni++)
#pragma unroll
                for (int j = 0; j < 4; j++)
                    co[mi][ni][j] *= al[mi][j >> 1];

        // ---- P = exp2(S*log2e - m*log2e) in half; stmatrix ----
#pragma unroll
        for (int mi = 0; mi < 2; mi++) {
#pragma unroll
            for (int np = 0; np < 4; np++) {
                int ni = 2 * np, ni1 = 2 * np + 1;
                uint32_t r0 = ex2h2(pkh2(fmaf(cs[mi][ni ][0], L2E, -ml[mi][0]),
                                         fmaf(cs[mi][ni ][1], L2E, -ml[mi][0])));
                uint32_t r1 = ex2h2(pkh2(fmaf(cs[mi][ni ][2], L2E, -ml[mi][1]),
                                         fmaf(cs[mi][ni ][3], L2E, -ml[mi][1])));
                uint32_t r2 = ex2h2(pkh2(fmaf(cs[mi][ni1][0], L2E, -ml[mi][0]),
                                         fmaf(cs[mi][ni1][1], L2E, -ml[mi][0])));
                uint32_t r3 = ex2h2(pkh2(fmaf(cs[mi][ni1][2], L2E, -ml[mi][1]),
                                         fmaf(cs[mi][ni1][3], L2E, -ml[mi][1])));
                stsm4(psb + moff[mi] + np * 32, r0, r1, r2, r3);
            }
        }
        __syncwarp();

        // ---- O += P @ V  and  l-rowsum via MMA with ones ----
        float csum[2][4];
#pragma unroll
        for (int mi = 0; mi < 2; mi++)
#pragma unroll
            for (int j = 0; j < 4; j++) csum[mi][j] = 0.f;

#pragma unroll
        for (int ks = 0; ks < 4; ks++) {
            uint32_t a[2][4], bf[8][2];
#pragma unroll
            for (int mi = 0; mi < 2; mi++)
                ldsm4(a[mi][0], a[mi][1], a[mi][2], a[mi][3],
                      psb + moff[mi] + ks * 32);
#pragma unroll
            for (int nn = 0; nn < 4; nn++) {
                uint32_t addr = vtile + ((ks << 4) + vrow) * ROWB + ((nn << 4) + vcol) * 2;
                ldsm4t(bf[2*nn][0], bf[2*nn][1], bf[2*nn+1][0], bf[2*nn+1][1], addr);
            }
#pragma unroll
            for (int mi = 0; mi < 2; mi++) {
                uint32_t bo[2] = {bones, bones};
                mma_f16(csum[mi], a[mi], bo);
#pragma unroll
                for (int ni = 0; ni < 8; ni++)
                    mma_f16(co[mi][ni], a[mi], bf[ni]);
            }
        }

#pragma unroll
        for (int mi = 0; mi < 2; mi++)
#pragma unroll
            for (int hh = 0; hh < 2; hh++)
                l_i[mi][hh] = l_i[mi][hh] * al[mi][hh] + csum[mi][2*hh];
    }

    // ---- epilogue ----
#pragma unroll
    for (int mi = 0; mi < 2; mi++)
#pragma unroll
        for (int hh = 0; hh < 2; hh++) {
            float inv = 1.f / l_i[mi][hh];
            int row = qt * 128 + wm + (mi << 4) + g + (hh << 3);
            __half* ob = O + ((size_t)(b * SS + row)) * DD + h * DKH;
#pragma unroll
            for (int ni = 0; ni < 8; ni++) {
                int col = (ni << 3) + (t << 1);
                *(uint32_t*)(ob + col) = pkh2(co[mi][ni][2*hh] * inv,
                                              co[mi][ni][2*hh+1] * inv);
            }
        }
}

// =============================================================================
// Launch
// =============================================================================
extern "C" void kernel_launch(void* const* d_in, const int* in_sizes, int n_in,
                              void* d_out, int out_size)
{
    const float* q  = (const float*)d_in[1];
    const float* k  = (const float*)d_in[2];
    const float* v  = (const float*)d_in[3];
    const float* wq = (const float*)d_in[5];
    const float* bq = (const float*)d_in[6];
    const float* wk = (const float*)d_in[7];
    const float* bk = (const float*)d_in[8];
    const float* wv = (const float*)d_in[9];
    const float* bv = (const float*)d_in[10];
    const float* wo = (const float*)d_in[11];
    const float* bo = (const float*)d_in[12];
    float* out = (float*)d_out;

    __half *aq, *ak, *av, *qh, *kh, *vh, *aoh, *wtq, *wtk, *wtv, *wto;
    cudaGetSymbolAddress((void**)&aq,  g_Aq);
    cudaGetSymbolAddress((void**)&ak,  g_Ak);
    cudaGetSymbolAddress((void**)&av,  g_Av);
    cudaGetSymbolAddress((void**)&qh,  g_Qh);
    cudaGetSymbolAddress((void**)&kh,  g_Kh);
    cudaGetSymbolAddress((void**)&vh,  g_Vh);
    cudaGetSymbolAddress((void**)&aoh, g_AOh);
    cudaGetSymbolAddress((void**)&wtq, g_Wq);
    cudaGetSymbolAddress((void**)&wtk, g_Wk);
    cudaGetSymbolAddress((void**)&wtv, g_Wv);
    cudaGetSymbolAddress((void**)&wto, g_Wo);

    cudaFuncSetAttribute(flash_f16_kernel,
                         cudaFuncAttributeMaxDynamicSharedMemorySize, ATT_SMEM);
    cudaFuncSetAttribute(gemm_qkv_f16,
                         cudaFuncAttributeMaxDynamicSharedMemorySize, G_SMEM);
    cudaFuncSetAttribute(gemm_o_f16,
                         cudaFuncAttributeMaxDynamicSharedMemorySize, G_SMEM);

    // ---- merged prepass (1 launch) ----
    prepass_kernel<<<ACT_BLOCKS + WT_BLOCKS, 256>>>(
        q, k, v, wq, wk, wv, wo,
        aq, ak, av, wtq, wtk, wtv, wto);

    // ---- fused QKV projections (R10 config) ----
    dim3 gblk(256);
    dim3 gqkv(DD / 128, MTOT / 128, 3);   // (8, 64, 3)
    gemm_qkv_f16<<<gqkv, gblk, G_SMEM>>>(aq, ak, av, wtq, wtk, wtv,
                                         bq, bk, bv, qh, kh, vh);

    // ---- attention (exact R10 config) ----
    dim3 agrid(SS / 128, HH, BB);         // (16, 16, 4)
    flash_f16_kernel<<<agrid, dim3(128), ATT_SMEM>>>(qh, kh, vh, aoh);

    // ---- output projection (R10 config, fp32 out) ----
    dim3 go(DD / 128, MTOT / 128);
    gemm_o_f16<<<go, gblk, G_SMEM>>>(aoh, wto, bo, out);
}

// round 16
// speedup vs baseline: 1.0399x; 1.0021x over previous
#include <cuda_runtime.h>
#include <cuda_fp16.h>
#include <math.h>
#include <stdint.h>

// Problem constants
#define BB 4
#define SS 2048
#define DD 1024
#define HH 16
#define DKH 64
#define MTOT (BB*SS)          // 8192 rows

#define L2E 1.4426950408889634f

// ---------------- scratch (static device globals; no allocation) -------------
__device__ __half g_Aq[MTOT*DD];
__device__ __half g_Ak[MTOT*DD];
__device__ __half g_Av[MTOT*DD];
__device__ __half g_Qh[MTOT*DD];
__device__ __half g_Kh[MTOT*DD];
__device__ __half g_Vh[MTOT*DD];
__device__ __half g_AOh[MTOT*DD];
__device__ __half g_Wq[DD*DD];     // WT[n][k] half (wq pre-scaled by 0.125)
__device__ __half g_Wk[DD*DD];
__device__ __half g_Wv[DD*DD];
__device__ __half g_Wo[DD*DD];

// ---------------- helpers -----------------------------------------------------
__device__ __forceinline__ uint32_t pkh2(float a, float b) {
    __half2 h = __floats2half2_rn(a, b);
    return *(uint32_t*)&h;
}
__device__ __forceinline__ uint32_t ex2h2(uint32_t x) {
    uint32_t r;
    asm("ex2.approx.f16x2 %0, %1;" : "=r"(r) : "r"(x));
    return r;
}
__device__ __forceinline__ void cpa16(uint32_t smem, const void* gmem) {
    asm volatile("cp.async.cg.shared.global [%0], [%1], 16;" :: "r"(smem), "l"(gmem));
}
__device__ __forceinline__ void cpa_commit() {
    asm volatile("cp.async.commit_group;");
}
template<int N> __device__ __forceinline__ void cpa_wait() {
    asm volatile("cp.async.wait_group %0;" :: "n"(N));
}
__device__ __forceinline__ uint32_t smem_u32(const void* p) {
    uint32_t a;
    asm("{ .reg .u64 t; cvta.to.shared.u64 t, %1; cvt.u32.u64 %0, t; }"
        : "=r"(a) : "l"(p));
    return a;
}
__device__ __forceinline__ void mma_f16(
    float c[4], const uint32_t a[4], const uint32_t b[2])
{
    asm volatile(
        "mma.sync.aligned.m16n8k16.row.col.f32.f16.f16.f32 "
        "{%0,%1,%2,%3}, {%4,%5,%6,%7}, {%8,%9}, {%0,%1,%2,%3};"
        : "+f"(c[0]), "+f"(c[1]), "+f"(c[2]), "+f"(c[3])
        : "r"(a[0]), "r"(a[1]), "r"(a[2]), "r"(a[3]),
          "r"(b[0]), "r"(b[1]));
}
__device__ __forceinline__ void ldsm4(
    uint32_t& r0, uint32_t& r1, uint32_t& r2, uint32_t& r3, uint32_t a)
{
    asm volatile("ldmatrix.sync.aligned.m8n8.x4.shared.b16 {%0,%1,%2,%3}, [%4];"
                 : "=r"(r0), "=r"(r1), "=r"(r2), "=r"(r3) : "r"(a));
}
__device__ __forceinline__ void ldsm4t(
    uint32_t& r0, uint32_t& r1, uint32_t& r2, uint32_t& r3, uint32_t a)
{
    asm volatile("ldmatrix.sync.aligned.m8n8.x4.trans.shared.b16 {%0,%1,%2,%3}, [%4];"
                 : "=r"(r0), "=r"(r1), "=r"(r2), "=r"(r3) : "r"(a));
}
__device__ __forceinline__ void stsm4(
    uint32_t a, uint32_t r0, uint32_t r1, uint32_t r2, uint32_t r3)
{
    asm volatile("stmatrix.sync.aligned.m8n8.x4.shared.b16 [%0], {%1,%2,%3,%4};"
                 :: "r"(a), "r"(r0), "r"(r1), "r"(r2), "r"(r3) : "memory");
}

// ---------------- merged prepass (one launch) ---------------------------------
#define ACT_BLOCKS (3 * (MTOT * DD / 4 / 256))   // 24576
#define WT_BLOCKS  (4 * (DD / 32) * (DD / 32))   // 4096

__global__ __launch_bounds__(256) void prepass_kernel(
    const float* __restrict__ q, const float* __restrict__ k,
    const float* __restrict__ v,
    const float* __restrict__ wq, const float* __restrict__ wk,
    const float* __restrict__ wv, const float* __restrict__ wo,
    __half* __restrict__ oaq, __half* __restrict__ oak, __half* __restrict__ oav,
    __half* __restrict__ owq, __half* __restrict__ owk,
    __half* __restrict__ owv, __half* __restrict__ owo)
{
    const int bx = blockIdx.x;
    const int tid = threadIdx.x;

    if (bx < ACT_BLOCKS) {
        const int which = bx / (ACT_BLOCKS / 3);
        const int blk   = bx % (ACT_BLOCKS / 3);
        const float* in = (which == 0) ? q : (which == 1) ? k : v;
        __half* out     = (which == 0) ? oaq : (which == 1) ? oak : oav;
        int i = blk * 256 + tid;
        float4 vv = ((const float4*)in)[i];
        uint2 o;
        o.x = pkh2(vv.x, vv.y);
        o.y = pkh2(vv.z, vv.w);
        ((uint2*)out)[i] = o;
    } else {
        const int w     = bx - ACT_BLOCKS;
        const int which = w >> 10;
        const int rem   = w & 1023;
        const int n0    = (rem & 31) << 5;
        const int k0    = (rem >> 5) << 5;
        const float* in = (which == 0) ? wq : (which == 1) ? wk : (which == 2) ? wv : wo;
        __half* out     = (which == 0) ? owq : (which == 1) ? owk : (which == 2) ? owv : owo;
        const float sc  = (which == 0) ? 0.125f : 1.0f;

        __shared__ float tl[32][33];
        const int tx = tid & 31, ty = tid >> 5;
#pragma unroll
        for (int i = 0; i < 4; i++)
            tl[ty + i * 8][tx] = in[(size_t)(k0 + ty + i * 8) * DD + n0 + tx];
        __syncthreads();
#pragma unroll
        for (int i = 0; i < 4; i++)
            out[(size_t)(n0 + ty + i * 8) * DD + k0 + tx] =
                __float2half(tl[tx][ty + i * 8] * sc);
    }
}

// =============================================================================
// FP16 HMMA GEMM (fused QKV) — R10 config + software-pipelined fragments:
// ldmatrix for k16 step ks+1 issues before the 16 MMAs of step ks.
// =============================================================================
#define HP 72
#define ROWB (HP*2)                       // 144 bytes per smem row
#define G_STG_H (2 * 128 * HP)
#define G_SMEM (3 * G_STG_H * 2)          // 110592 bytes
#define GNT (DD / 64)                     // 16 K-iterations

__global__ __launch_bounds__(256) void gemm_qkv_f16(
    const __half* __restrict__ A0, const __half* __restrict__ A1,
    const __half* __restrict__ A2,
    const __half* __restrict__ W0, const __half* __restrict__ W1,
    const __half* __restrict__ W2,
    const float* __restrict__ b0, const float* __restrict__ b1,
    const float* __restrict__ b2,
    __half* __restrict__ C0, __half* __restrict__ C1, __half* __restrict__ C2)
{
    extern __shared__ __half shh[];

    const int z = blockIdx.z;
    const __half* A  = (z == 0) ? A0 : (z == 1) ? A1 : A2;
    const __half* WT = (z == 0) ? W0 : (z == 1) ? W1 : W2;
    const float* bias = (z == 0) ? b0 : (z == 1) ? b1 : b2;
    __half* C        = (z == 0) ? C0 : (z == 1) ? C1 : C2;
    const float bsc  = (z == 0) ? 0.125f : 1.0f;

    const int tid  = threadIdx.x;
    const int wid  = tid >> 5;
    const int lane = tid & 31;
    const int g    = lane >> 2;
    const int t    = lane & 3;
    const int wm   = (wid & 3) << 5;
    const int wn   = (wid >> 2) << 6;
    const int m0   = blockIdx.y << 7;
    const int n0   = blockIdx.x << 7;

    const int lj = lane >> 3, lr = lane & 7;
    uint32_t aoff[2], boff[4];
#pragma unroll
    for (int mi = 0; mi < 2; mi++)
        aoff[mi] = (uint32_t)(((wm + (mi << 4) + ((lj & 1) << 3) + lr) * HP
                               + ((lj >> 1) << 3)) * 2);
#pragma unroll
    for (int np = 0; np < 4; np++)
        boff[np] = (uint32_t)(((wn + (np << 4) + ((lj & 1) << 3) + lr) * HP
                               + ((lj >> 1) << 3)) * 2);

    float c[2][8][4];
#pragma unroll
    for (int mi = 0; mi < 2; mi++)
#pragma unroll
        for (int ni = 0; ni < 8; ni++)
#pragma unroll
            for (int j = 0; j < 4; j++) c[mi][ni][j] = 0.f;

    const uint32_t shbase = smem_u32(shh);

    auto load_tile = [&](int kt, int stg) {
        const int k0 = kt << 6;
        const uint32_t sa = shbase + (stg * G_STG_H) * 2;
        const uint32_t sb = sa + 128 * ROWB;
#pragma unroll
        for (int j = 0; j < 4; j++) {
            int ca = j * 256 + tid;
            int row = ca >> 3, k8 = ca & 7;
            cpa16(sa + row * ROWB + (k8 << 4),
                  A + (size_t)(m0 + row) * DD + k0 + (k8 << 3));
        }
#pragma unroll
        for (int j = 0; j < 4; j++) {
            int cb = j * 256 + tid;
            int row = cb >> 3, k8 = cb & 7;
            cpa16(sb + row * ROWB + (k8 << 4),
                  WT + (size_t)(n0 + row) * DD + k0 + (k8 << 3));
        }
        cpa_commit();
    };

    load_tile(0, 0);
    load_tile(1, 1);

    for (int kt = 0; kt < GNT; kt++) {
        if (kt + 1 < GNT) cpa_wait<1>(); else cpa_wait<0>();
        __syncthreads();
        if (kt + 2 < GNT) load_tile(kt + 2, (kt + 2) % 3);

        const int stg = kt % 3;
        const uint32_t sa = shbase + (stg * G_STG_H) * 2;
        const uint32_t sb = sa + 128 * ROWB;

        // software-pipelined fragments: double-buffer over ks
        uint32_t af[2][2][4], bf[2][8][2];

        auto load_frag = [&](int ks, int p) {
#pragma unroll
            for (int mi = 0; mi < 2; mi++)
                ldsm4(af[p][mi][0], af[p][mi][1], af[p][mi][2], af[p][mi][3],
                      sa + aoff[mi] + ks * 32);
#pragma unroll
            for (int np = 0; np < 4; np++)
                ldsm4(bf[p][2*np][0], bf[p][2*np+1][0],
                      bf[p][2*np][1], bf[p][2*np+1][1],
                      sb + boff[np] + ks * 32);
        };

        load_frag(0, 0);
#pragma unroll
        for (int ks = 0; ks < 4; ks++) {
            const int p = ks & 1;
            if (ks < 3) load_frag(ks + 1, p ^ 1);
#pragma unroll
            for (int mi = 0; mi < 2; mi++)
#pragma unroll
                for (int ni = 0; ni < 8; ni++)
                    mma_f16(c[mi][ni], af[p][mi], bf[p][ni]);
        }
    }

#pragma unroll
    for (int ni = 0; ni < 8; ni++) {
        int col = n0 + wn + (ni << 3) + (t << 1);
        float2 bv = *(const float2*)(bias + col);
        bv.x *= bsc; bv.y *= bsc;
#pragma unroll
        for (int mi = 0; mi < 2; mi++) {
            int row = m0 + wm + (mi << 4) + g;
            *(uint32_t*)(C + (size_t)row       * DD + col) =
                pkh2(c[mi][ni][0] + bv.x, c[mi][ni][1] + bv.y);
            *(uint32_t*)(C + (size_t)(row + 8) * DD + col) =
                pkh2(c[mi][ni][2] + bv.x, c[mi][ni][3] + bv.y);
        }
    }
}

// Single GEMM (output projection, fp32 out) — same pipelined core.
__global__ __launch_bounds__(256) void gemm_o_f16(
    const __half* __restrict__ A, const __half* __restrict__ WT,
    const float* __restrict__ bias, float* __restrict__ C)
{
    extern __shared__ __half shh[];

    const int tid  = threadIdx.x;
    const int wid  = tid >> 5;
    const int lane = tid & 31;
    const int g    = lane >> 2;
    const int t    = lane & 3;
    const int wm   = (wid & 3) << 5;
    const int wn   = (wid >> 2) << 6;
    const int m0   = blockIdx.y << 7;
    const int n0   = blockIdx.x << 7;

    const int lj = lane >> 3, lr = lane & 7;
    uint32_t aoff[2], boff[4];
#pragma unroll
    for (int mi = 0; mi < 2; mi++)
        aoff[mi] = (uint32_t)(((wm + (mi << 4) + ((lj & 1) << 3) + lr) * HP
                               + ((lj >> 1) << 3)) * 2);
#pragma unroll
    for (int np = 0; np < 4; np++)
        boff[np] = (uint32_t)(((wn + (np << 4) + ((lj & 1) << 3) + lr) * HP
                               + ((lj >> 1) << 3)) * 2);

    float c[2][8][4];
#pragma unroll
    for (int mi = 0; mi < 2; mi++)
#pragma unroll
        for (int ni = 0; ni < 8; ni++)
#pragma unroll
            for (int j = 0; j < 4; j++) c[mi][ni][j] = 0.f;

    const uint32_t shbase = smem_u32(shh);

    auto load_tile = [&](int kt, int stg) {
        const int k0 = kt << 6;
        const uint32_t sa = shbase + (stg * G_STG_H) * 2;
        const uint32_t sb = sa + 128 * ROWB;
#pragma unroll
        for (int j = 0; j < 4; j++) {
            int ca = j * 256 + tid;
            int row = ca >> 3, k8 = ca & 7;
            cpa16(sa + row * ROWB + (k8 << 4),
                  A + (size_t)(m0 + row) * DD + k0 + (k8 << 3));
        }
#pragma unroll
        for (int j = 0; j < 4; j++) {
            int cb = j * 256 + tid;
            int row = cb >> 3, k8 = cb & 7;
            cpa16(sb + row * ROWB + (k8 << 4),
                  WT + (size_t)(n0 + row) * DD + k0 + (k8 << 3));
        }
        cpa_commit();
    };

    load_tile(0, 0);
    load_tile(1, 1);

    for (int kt = 0; kt < GNT; kt++) {
        if (kt + 1 < GNT) cpa_wait<1>(); else cpa_wait<0>();
        __syncthreads();
        if (kt + 2 < GNT) load_tile(kt + 2, (kt + 2) % 3);

        const int stg = kt % 3;
        const uint32_t sa = shbase + (stg * G_STG_H) * 2;
        const uint32_t sb = sa + 128 * ROWB;

        uint32_t af[2][2][4], bf[2][8][2];

        auto load_frag = [&](int ks, int p) {
#pragma unroll
            for (int mi = 0; mi < 2; mi++)
                ldsm4(af[p][mi][0], af[p][mi][1], af[p][mi][2], af[p][mi][3],
                      sa + aoff[mi] + ks * 32);
#pragma unroll
            for (int np = 0; np < 4; np++)
                ldsm4(bf[p][2*np][0], bf[p][2*np+1][0],
                      bf[p][2*np][1], bf[p][2*np+1][1],
                      sb + boff[np] + ks * 32);
        };

        load_frag(0, 0);
#pragma unroll
        for (int ks = 0; ks < 4; ks++) {
            const int p = ks & 1;
            if (ks < 3) load_frag(ks + 1, p ^ 1);
#pragma unroll
            for (int mi = 0; mi < 2; mi++)
#pragma unroll
                for (int ni = 0; ni < 8; ni++)
                    mma_f16(c[mi][ni], af[p][mi], bf[p][ni]);
        }
    }

#pragma unroll
    for (int ni = 0; ni < 8; ni++) {
        int col = n0 + wn + (ni << 3) + (t << 1);
        float2 bv = *(const float2*)(bias + col);
#pragma unroll
        for (int mi = 0; mi < 2; mi++) {
            int row = m0 + wm + (mi << 4) + g;
            float2 v0 = make_float2(c[mi][ni][0] + bv.x, c[mi][ni][1] + bv.y);
            float2 v1 = make_float2(c[mi][ni][2] + bv.x, c[mi][ni][3] + bv.y);
            *(float2*)(C + (size_t)row       * DD + col) = v0;
            *(float2*)(C + (size_t)(row + 8) * DD + col) = v1;
        }
    }
}

// =============================================================================
// FP16 flash attention (causal) — exact R10 kernel (untouched).
// =============================================================================
#define ATT_SMEM ((128*HP + 2*64*HP + 2*64*HP + 128*HP) * 2)

__global__ __launch_bounds__(128) void flash_f16_kernel(
    const __half* __restrict__ Q, const __half* __restrict__ K,
    const __half* __restrict__ V, __half* __restrict__ O)
{
    const int qt = (SS / 128 - 1) - blockIdx.x;
    const int h  = blockIdx.y;
    const int b  = blockIdx.z;
    const int tid  = threadIdx.x;
    const int warp = tid >> 5;
    const int lane = tid & 31;
    const int g    = lane >> 2;
    const int t    = lane & 3;
    const int wm   = warp << 5;

    extern __shared__ __half smh[];
    __half* Qs = smh;                    // [128][HP]
    __half* Ks = Qs + 128 * HP;          // [2][64][HP]
    __half* Vs = Ks + 2 * 64 * HP;       // [2][64][HP]
    __half* Ps = Vs + 2 * 64 * HP;       // [128][HP]

    const uint32_t qsb = smem_u32(Qs);
    const uint32_t ksbase = smem_u32(Ks);
    const uint32_t vsbase = smem_u32(Vs);
    const uint32_t psb = smem_u32(Ps);

    const int lj = lane >> 3, lr = lane & 7;
    uint32_t moff[2], koff[4];
#pragma unroll
    for (int mi = 0; mi < 2; mi++)
        moff[mi] = (uint32_t)(((wm + (mi << 4) + ((lj & 1) << 3) + lr) * HP
                               + ((lj >> 1) << 3)) * 2);
#pragma unroll
    for (int np = 0; np < 4; np++)
        koff[np] = (uint32_t)((((np << 4) + ((lj & 1) << 3) + lr) * HP
                               + ((lj >> 1) << 3)) * 2);

    const int vrow = ((lane >> 3) & 1) * 8 + (lane & 7);
    const int vcol = (lane >> 4) * 8;

    const __half* Kh0 = K + ((size_t)(b * SS)) * DD + h * DKH;
    const __half* Vh0 = V + ((size_t)(b * SS)) * DD + h * DKH;

    auto load_kv = [&](int kt, int buf) {
        const __half* Kb = Kh0 + (size_t)(kt * 64) * DD;
        const __half* Vb = Vh0 + (size_t)(kt * 64) * DD;
        const uint32_t kb = ksbase + buf * 64 * ROWB;
        const uint32_t vb = vsbase + buf * 64 * ROWB;
#pragma unroll
        for (int i = 0; i < 4; i++) {
            int e = i * 128 + tid;
            int r = e >> 3;
            int c8 = e & 7;
            cpa16(kb + r * ROWB + (c8 << 4), Kb + (size_t)r * DD + (c8 << 3));
            cpa16(vb + r * ROWB + (c8 << 4), Vb + (size_t)r * DD + (c8 << 3));
        }
        cpa_commit();
    };

    // ---- load Q tile ----
    const __half* Qb = Q + ((size_t)(b * SS + qt * 128)) * DD + h * DKH;
#pragma unroll
    for (int i = 0; i < 8; i++) {
        int e = i * 128 + tid;
        int r = e >> 3;
        int c8 = e & 7;
        *(uint4*)&Qs[r * HP + (c8 << 3)] = *(const uint4*)(Qb + (size_t)r * DD + (c8 << 3));
    }

    load_kv(0, 0);

    float m_i[2][2], l_i[2][2], co[2][8][4];
#pragma unroll
    for (int mi = 0; mi < 2; mi++)
#pragma unroll
        for (int hh = 0; hh < 2; hh++) { m_i[mi][hh] = -INFINITY; l_i[mi][hh] = 0.f; }
#pragma unroll
    for (int mi = 0; mi < 2; mi++)
#pragma unroll
        for (int ni = 0; ni < 8; ni++)
#pragma unroll
            for (int j = 0; j < 4; j++) co[mi][ni][j] = 0.f;

    const uint32_t bones = 0x3C003C00u;  // half2(1,1)
    const int ktmax = 2 * qt + 1;

    for (int kt = 0; kt <= ktmax; kt++) {
        __syncthreads();
        if (kt < ktmax) {
            load_kv(kt + 1, (kt + 1) & 1);
            cpa_wait<1>();
        } else {
            cpa_wait<0>();
        }
        __syncthreads();

        const uint32_t ktile = ksbase + (kt & 1) * 64 * ROWB;
        const uint32_t vtile = vsbase + (kt & 1) * 64 * ROWB;

        // ---- S = Q K^T (pre-scaled via wq) ----
        float cs[2][8][4];
#pragma unroll
        for (int mi = 0; mi < 2; mi++)
#pragma unroll
            for (int ni = 0; ni < 8; ni++)
#pragma unroll
                for (int j = 0; j < 4; j++) cs[mi][ni][j] = 0.f;

#pragma unroll
        for (int ks = 0; ks < 4; ks++) {
            uint32_t a[2][4], bf[8][2];
#pragma unroll
            for (int mi = 0; mi < 2; mi++)
                ldsm4(a[mi][0], a[mi][1], a[mi][2], a[mi][3],
                      qsb + moff[mi] + ks * 32);
#pragma unroll
            for (int np = 0; np < 4; np++)
                ldsm4(bf[2*np][0], bf[2*np+1][0], bf[2*np][1], bf[2*np+1][1],
                      ktile + koff[np] + ks * 32);
#pragma unroll
            for (int mi = 0; mi < 2; mi++)
#pragma unroll
                for (int ni = 0; ni < 8; ni++)
                    mma_f16(cs[mi][ni], a[mi], bf[ni]);
        }

        // ---- causal mask (only last two tiles) ----
        if (kt >= 2 * qt) {
#pragma unroll
            for (int mi = 0; mi < 2; mi++)
#pragma unroll
                for (int ni = 0; ni < 8; ni++)
#pragma unroll
                    for (int j = 0; j < 4; j++) {
                        int row = qt * 128 + wm + (mi << 4) + g + ((j >> 1) << 3);
                        int col = kt * 64 + (ni << 3) + (t << 1) + (j & 1);
                        if (col > row) cs[mi][ni][j] = -1e9f;
                    }
        }

        // ---- online softmax: max + alpha ----
        float ml[2][2], al[2][2];
#pragma unroll
        for (int mi = 0; mi < 2; mi++)
#pragma unroll
            for (int hh = 0; hh < 2; hh++) {
                float mx = -INFINITY;
#pragma unroll
                for (int ni = 0; ni < 8; ni++)
                    mx = fmaxf(mx, fmaxf(cs[mi][ni][2*hh], cs[mi][ni][2*hh+1]));
                mx = fmaxf(mx, __shfl_xor_sync(0xffffffffu, mx, 1));
                mx = fmaxf(mx, __shfl_xor_sync(0xffffffffu, mx, 2));
                float m2 = fmaxf(m_i[mi][hh], mx);
                al[mi][hh] = __expf(m_i[mi][hh] - m2);
                m_i[mi][hh] = m2;
                ml[mi][hh] = m2 * L2E;
            }
#pragma unroll
        for (int mi = 0; mi < 2; mi++)
#pragma unroll
            for (int ni = 0; ni < 8; ni++)
#pragma unroll
                for (int j = 0; j < 4; j++)
                    co[mi][ni][j] *= al[mi][j >> 1];

        // ---- P = exp2(S*log2e - m*log2e) in half; stmatrix ----
#pragma unroll
        for (int mi = 0; mi < 2; mi++) {
#pragma unroll
            for (int np = 0; np < 4; np++) {
                int ni = 2 * np, ni1 = 2 * np + 1;
                uint32_t r0 = ex2h2(pkh2(fmaf(cs[mi][ni ][0], L2E, -ml[mi][0]),
                                         fmaf(cs[mi][ni ][1], L2E, -ml[mi][0])));
                uint32_t r1 = ex2h2(pkh2(fmaf(cs[mi][ni ][2], L2E, -ml[mi][1]),
                                         fmaf(cs[mi][ni ][3], L2E, -ml[mi][1])));
                uint32_t r2 = ex2h2(pkh2(fmaf(cs[mi][ni1][0], L2E, -ml[mi][0]),
                                         fmaf(cs[mi][ni1][1], L2E, -ml[mi][0])));
                uint32_t r3 = ex2h2(pkh2(fmaf(cs[mi][ni1][2], L2E, -ml[mi][1]),
                                         fmaf(cs[mi][ni1][3], L2E, -ml[mi][1])));
                stsm4(psb + moff[mi] + np * 32, r0, r1, r2, r3);
            }
        }
        __syncwarp();

        // ---- O += P @ V  and  l-rowsum via MMA with ones ----
        float csum[2][4];
#pragma unroll
        for (int mi = 0; mi < 2; mi++)
#pragma unroll
            for (int j = 0; j < 4; j++) csum[mi][j] = 0.f;

#pragma unroll
        for (int ks = 0; ks < 4; ks++) {
            uint32_t a[2][4], bf[8][2];
#pragma unroll
            for (int mi = 0; mi < 2; mi++)
                ldsm4(a[mi][0], a[mi][1], a[mi][2], a[mi][3],
                      psb + moff[mi] + ks * 32);
#pragma unroll
            for (int nn = 0; nn < 4; nn++) {
                uint32_t addr = vtile + ((ks << 4) + vrow) * ROWB + ((nn << 4) + vcol) * 2;
                ldsm4t(bf[2*nn][0], bf[2*nn][1], bf[2*nn+1][0], bf[2*nn+1][1], addr);
            }
#pragma unroll
            for (int mi = 0; mi < 2; mi++) {
                uint32_t bo[2] = {bones, bones};
                mma_f16(csum[mi], a[mi], bo);
#pragma unroll
                for (int ni = 0; ni < 8; ni++)
                    mma_f16(co[mi][ni], a[mi], bf[ni]);
            }
        }

#pragma unroll
        for (int mi = 0; mi < 2; mi++)
#pragma unroll
            for (int hh = 0; hh < 2; hh++)
                l_i[mi][hh] = l_i[mi][hh] * al[mi][hh] + csum[mi][2*hh];
    }

    // ---- epilogue ----
#pragma unroll
    for (int mi = 0; mi < 2; mi++)
#pragma unroll
        for (int hh = 0; hh < 2; hh++) {
            float inv = 1.f / l_i[mi][hh];
            int row = qt * 128 + wm + (mi << 4) + g + (hh << 3);
            __half* ob = O + ((size_t)(b * SS + row)) * DD + h * DKH;
#pragma unroll
            for (int ni = 0; ni < 8; ni++) {
                int col = (ni << 3) + (t << 1);
                *(uint32_t*)(ob + col) = pkh2(co[mi][ni][2*hh] * inv,
                                              co[mi][ni][2*hh+1] * inv);
            }
        }
}

// =============================================================================
// Launch
// =============================================================================
extern "C" void kernel_launch(void* const* d_in, const int* in_sizes, int n_in,
                              void* d_out, int out_size)
{
    const float* q  = (const float*)d_in[1];
    const float* k  = (const float*)d_in[2];
    const float* v  = (const float*)d_in[3];
    const float* wq = (const float*)d_in[5];
    const float* bq = (const float*)d_in[6];
    const float* wk = (const float*)d_in[7];
    const float* bk = (const float*)d_in[8];
    const float* wv = (const float*)d_in[9];
    const float* bv = (const float*)d_in[10];
    const float* wo = (const float*)d_in[11];
    const float* bo = (const float*)d_in[12];
    float* out = (float*)d_out;

    __half *aq, *ak, *av, *qh, *kh, *vh, *aoh, *wtq, *wtk, *wtv, *wto;
    cudaGetSymbolAddress((void**)&aq,  g_Aq);
    cudaGetSymbolAddress((void**)&ak,  g_Ak);
    cudaGetSymbolAddress((void**)&av,  g_Av);
    cudaGetSymbolAddress((void**)&qh,  g_Qh);
    cudaGetSymbolAddress((void**)&kh,  g_Kh);
    cudaGetSymbolAddress((void**)&vh,  g_Vh);
    cudaGetSymbolAddress((void**)&aoh, g_AOh);
    cudaGetSymbolAddress((void**)&wtq, g_Wq);
    cudaGetSymbolAddress((void**)&wtk, g_Wk);
    cudaGetSymbolAddress((void**)&wtv, g_Wv);
    cudaGetSymbolAddress((void**)&wto, g_Wo);

    cudaFuncSetAttribute(flash_f16_kernel,
                         cudaFuncAttributeMaxDynamicSharedMemorySize, ATT_SMEM);
    cudaFuncSetAttribute(gemm_qkv_f16,
                         cudaFuncAttributeMaxDynamicSharedMemorySize, G_SMEM);
    cudaFuncSetAttribute(gemm_o_f16,
                         cudaFuncAttributeMaxDynamicSharedMemorySize, G_SMEM);

    // ---- merged prepass (1 launch) ----
    prepass_kernel<<<ACT_BLOCKS + WT_BLOCKS, 256>>>(
        q, k, v, wq, wk, wv, wo,
        aq, ak, av, wtq, wtk, wtv, wto);

    // ---- fused QKV projections ----
    dim3 gblk(256);
    dim3 gqkv(DD / 128, MTOT / 128, 3);   // (8, 64, 3)
    gemm_qkv_f16<<<gqkv, gblk, G_SMEM>>>(aq, ak, av, wtq, wtk, wtv,
                                         bq, bk, bv, qh, kh, vh);

    // ---- attention (exact R10 config) ----
    dim3 agrid(SS / 128, HH, BB);         // (16, 16, 4)
    flash_f16_kernel<<<agrid, dim3(128), ATT_SMEM>>>(qh, kh, vh, aoh);

    // ---- output projection (fp32 out) ----
    dim3 go(DD / 128, MTOT / 128);
    gemm_o_f16<<<go, gblk, G_SMEM>>>(aoh, wto, bo, out);
}